// round 1
// baseline (speedup 1.0000x reference)
#include <cuda_runtime.h>
#include <math.h>

// ---------------------------------------------------------------------------
// ResBlock (StyleGAN2-D style) on GB300.
// Pipeline:
//   sigma_i = ||W_i (W_i^T u_i)|| / ||W_i^T u_i||   (one power iteration; v input unused)
//   a   = lrelu( conv3x3(x, w1/s1, pad1) + b1 )
//   c   = blur4x4(a, pad=2)                  -> 65x65
//   out = lrelu( conv3x3_s2(c, w2/s2) + b2 ) -> 32x32 (written to d_out)
//   bB  = blur4x4(x, pad=1)                  -> 63x63
//   d_out = (d_out + conv1x1_s2(bB, ws/ss)) / sqrt(2)
// ---------------------------------------------------------------------------

#define RSQRT2 0.70710678118654752f

// ---- device scratch (allocation-free rule: static __device__ globals) ----
__device__ float g_inv_sigma[3];
__device__ float g_t[2304];                      // W^T u scratch (reused sequentially)
__device__ float g_s[512];                       // W (W^T u) scratch
__device__ float g_bufA[16 * 256 * 64 * 64];     // conv1 output
__device__ float g_bufB[16 * 256 * 63 * 63];     // blur(x, pad=1)
__device__ float g_bufC[16 * 256 * 65 * 65];     // blur(conv1 out, pad=2)

// ---------------------------------------------------------------------------
// reductions
// ---------------------------------------------------------------------------
__device__ __forceinline__ float warp_sum(float v) {
#pragma unroll
    for (int o = 16; o; o >>= 1) v += __shfl_down_sync(0xffffffffu, v, o);
    return v;
}

__device__ float block_sum(float v) {
    __shared__ float red[32];
    int lane = threadIdx.x & 31, w = threadIdx.x >> 5;
    v = warp_sum(v);
    if (lane == 0) red[w] = v;
    __syncthreads();
    float r = 0.f;
    if (w == 0) {
        int nw = (blockDim.x + 31) >> 5;
        r = (lane < nw) ? red[lane] : 0.f;
        r = warp_sum(r);
    }
    __syncthreads();   // safe to reuse `red` on next call
    return r;          // valid in thread 0
}

// ---------------------------------------------------------------------------
// spectral norm: three small kernels
// ---------------------------------------------------------------------------
// t = W^T u   (W is [H, K] row-major)
__global__ void sn_tk(const float* __restrict__ W, const float* __restrict__ u,
                      int H, int K) {
    __shared__ float us[512];
    for (int i = threadIdx.x; i < H; i += blockDim.x) us[i] = u[i];
    __syncthreads();
    int j = blockIdx.x * blockDim.x + threadIdx.x;
    if (j >= K) return;
    float s = 0.f;
    for (int i = 0; i < H; i++) s = fmaf(W[(size_t)i * K + j], us[i], s);
    g_t[j] = s;
}

// s_i = W[i,:] . t   (one block per row)
__global__ void sn_sk(const float* __restrict__ W, int K) {
    int i = blockIdx.x;
    float s = 0.f;
    for (int j = threadIdx.x; j < K; j += blockDim.x)
        s = fmaf(W[(size_t)i * K + j], g_t[j], s);
    s = block_sum(s);
    if (threadIdx.x == 0) g_s[i] = s;
}

// inv_sigma from ||t|| and ||W t||
__global__ void sn_fin(int H, int K, int idx) {
    float a = 0.f;
    for (int j = threadIdx.x; j < K; j += blockDim.x) {
        float t = g_t[j];
        a = fmaf(t, t, a);
    }
    float aT = block_sum(a);
    float b = 0.f;
    for (int i = threadIdx.x; i < H; i += blockDim.x) {
        float t = g_s[i];
        b = fmaf(t, t, b);
    }
    float bT = block_sum(b);
    if (threadIdx.x == 0) {
        float nt = sqrtf(aT);           // ||W^T u||
        float nwt = sqrtf(bT);          // ||W (W^T u)||
        float nwv = nwt / (nt + 1e-12f);             // ||W v||
        float sigma = nwv * nwv / (nwv + 1e-12f);    // u'.(Wv)
        g_inv_sigma[idx] = 1.f / sigma;
    }
}

// ---------------------------------------------------------------------------
// 4x4 binomial blur (depthwise, zero-pad P, VALID) : OHW = IHW + 2P - 3
// ---------------------------------------------------------------------------
__global__ void blur_kernel(const float* __restrict__ in, float* __restrict__ out,
                            int NC, int IHW, int P, int OHW) {
    int idx = blockIdx.x * blockDim.x + threadIdx.x;
    int total = NC * OHW * OHW;
    if (idx >= total) return;
    int x = idx % OHW;
    int t = idx / OHW;
    int y = t % OHW;
    int nc = t / OHW;
    const float* ip = in + (size_t)nc * IHW * IHW;
    const float kv[4] = {1.f, 3.f, 3.f, 1.f};
    float s = 0.f;
#pragma unroll
    for (int i = 0; i < 4; i++) {
        int yy = y + i - P;
        if ((unsigned)yy >= (unsigned)IHW) continue;
#pragma unroll
        for (int j = 0; j < 4; j++) {
            int xx = x + j - P;
            if ((unsigned)xx >= (unsigned)IHW) continue;
            s = fmaf(kv[i] * kv[j], ip[(size_t)yy * IHW + xx], s);
        }
    }
    out[idx] = s * (1.f / 64.f);
}

// ---------------------------------------------------------------------------
// 3x3 conv, implicit GEMM, shared-memory tiled, fused inv_sigma + bias + lrelu
//   grid = (OH, OC/(16*OCPT), N), block = 256
//   per-thread tile: OCPT output channels x OWPT output columns
// ---------------------------------------------------------------------------
template <int IC, int OCPT, int OWPT, int OW, int STRIDE, int PAD, int IH, int IW>
__global__ void conv3x3_kernel(const float* __restrict__ in,
                               const float* __restrict__ wgt,
                               const float* __restrict__ bias,
                               float* __restrict__ out,
                               int OC, int sigIdx, int OH) {
    constexpr int OCT = 16 * OCPT;
    constexpr int IWN = (OW - 1) * STRIDE + 3;
    constexpr int ICC = 8;
    constexpr int WSW = ICC * 9 + 1;  // 73: padded to dodge bank conflicts

    __shared__ float xs[ICC * 3 * IWN];
    __shared__ float ws[OCT * WSW];

    const int tid = threadIdx.x;
    const int tx = tid & 15;        // output-column group (ow = tx + i*16)
    const int ty = tid >> 4;        // output-channel group
    const int oh = blockIdx.x;
    const int ocb = blockIdx.y * OCT;
    const int n = blockIdx.z;

    float acc[OCPT][OWPT];
#pragma unroll
    for (int j = 0; j < OCPT; j++)
#pragma unroll
        for (int i = 0; i < OWPT; i++) acc[j][i] = 0.f;

    const float* inN = in + (size_t)n * IC * IH * IW;

    for (int ic0 = 0; ic0 < IC; ic0 += ICC) {
        __syncthreads();
        // input slab: ICC channels x 3 rows x IWN columns (zero padded)
        for (int e = tid; e < ICC * 3 * IWN; e += 256) {
            int ic = e / (3 * IWN);
            int rem = e - ic * (3 * IWN);
            int r = rem / IWN;
            int c = rem - r * IWN;
            int ih = oh * STRIDE - PAD + r;
            int iw = c - PAD;
            float v = 0.f;
            if ((unsigned)ih < (unsigned)IH && (unsigned)iw < (unsigned)IW)
                v = inN[((size_t)(ic0 + ic) * IH + ih) * IW + iw];
            xs[e] = v;
        }
        // weights: OCT x (ICC*9), k = ic*9 + kh*3 + kw (contiguous in gmem)
        for (int e = tid; e < OCT * ICC * 9; e += 256) {
            int oc = e / (ICC * 9);
            int k = e - oc * (ICC * 9);
            ws[oc * WSW + k] = wgt[((size_t)(ocb + oc) * IC + ic0) * 9 + k];
        }
        __syncthreads();

        for (int ic = 0; ic < ICC; ic++) {
#pragma unroll
            for (int kh = 0; kh < 3; kh++) {
#pragma unroll
                for (int kw = 0; kw < 3; kw++) {
                    float a[OWPT], b[OCPT];
#pragma unroll
                    for (int i = 0; i < OWPT; i++)
                        a[i] = xs[(ic * 3 + kh) * IWN + (tx + i * 16) * STRIDE + kw];
#pragma unroll
                    for (int j = 0; j < OCPT; j++)
                        b[j] = ws[(ty * OCPT + j) * WSW + ic * 9 + kh * 3 + kw];
#pragma unroll
                    for (int j = 0; j < OCPT; j++)
#pragma unroll
                        for (int i = 0; i < OWPT; i++)
                            acc[j][i] = fmaf(b[j], a[i], acc[j][i]);
                }
            }
        }
    }

    const float is = g_inv_sigma[sigIdx];
#pragma unroll
    for (int j = 0; j < OCPT; j++) {
        int oc = ocb + ty * OCPT + j;
        float bv = bias[oc];
#pragma unroll
        for (int i = 0; i < OWPT; i++) {
            float v = fmaf(acc[j][i], is, bv);
            v = v > 0.f ? v : 0.2f * v;
            out[(((size_t)n * OC + oc) * OH + oh) * OW + tx + i * 16] = v;
        }
    }
}

// ---------------------------------------------------------------------------
// skip: 1x1 stride-2 conv on blur(x) [16,256,63,63] -> add into d_out, /sqrt(2)
//   grid = (32, 512/128, 16), block = 256; per-thread 8 oc x 2 ow
// ---------------------------------------------------------------------------
__global__ void skip1x1_kernel(const float* __restrict__ in,
                               const float* __restrict__ wgt,
                               float* __restrict__ out) {
    __shared__ float xs[16 * 32];
    __shared__ float ws[128 * 17];
    const int tid = threadIdx.x;
    const int tx = tid & 15, ty = tid >> 4;
    const int oh = blockIdx.x;
    const int ocb = blockIdx.y * 128;
    const int n = blockIdx.z;

    float acc[8][2];
#pragma unroll
    for (int j = 0; j < 8; j++) { acc[j][0] = 0.f; acc[j][1] = 0.f; }

    const float* inN = in + (size_t)n * 256 * 63 * 63 + (size_t)(oh * 2) * 63;

    for (int ic0 = 0; ic0 < 256; ic0 += 16) {
        __syncthreads();
        for (int e = tid; e < 512; e += 256) {
            int ic = e >> 5, owx = e & 31;
            xs[e] = inN[(size_t)(ic0 + ic) * 63 * 63 + owx * 2];
        }
        for (int e = tid; e < 2048; e += 256) {
            int oc = e >> 4, ic = e & 15;
            ws[oc * 17 + ic] = wgt[(size_t)(ocb + oc) * 256 + ic0 + ic];
        }
        __syncthreads();
        for (int ic = 0; ic < 16; ic++) {
            float a0 = xs[ic * 32 + tx];
            float a1 = xs[ic * 32 + tx + 16];
#pragma unroll
            for (int j = 0; j < 8; j++) {
                float b = ws[(ty * 8 + j) * 17 + ic];
                acc[j][0] = fmaf(b, a0, acc[j][0]);
                acc[j][1] = fmaf(b, a1, acc[j][1]);
            }
        }
    }

    const float is = g_inv_sigma[2];
#pragma unroll
    for (int j = 0; j < 8; j++) {
        int oc = ocb + ty * 8 + j;
        size_t base = (((size_t)n * 512 + oc) * 32 + oh) * 32;
#pragma unroll
        for (int i = 0; i < 2; i++) {
            size_t idx = base + tx + i * 16;
            out[idx] = (out[idx] + acc[j][i] * is) * RSQRT2;
        }
    }
}

// ---------------------------------------------------------------------------
// launch
// ---------------------------------------------------------------------------
extern "C" void kernel_launch(void* const* d_in, const int* in_sizes, int n_in,
                              void* d_out, int out_size) {
    const float* x   = (const float*)d_in[0];
    const float* w1  = (const float*)d_in[1];
    const float* u1  = (const float*)d_in[2];
    const float* b1  = (const float*)d_in[4];
    const float* w2  = (const float*)d_in[5];
    const float* u2  = (const float*)d_in[6];
    const float* b2  = (const float*)d_in[8];
    const float* wsk = (const float*)d_in[9];
    const float* us  = (const float*)d_in[10];
    float* out = (float*)d_out;

    float *bufA, *bufB, *bufC;
    cudaGetSymbolAddress((void**)&bufA, g_bufA);
    cudaGetSymbolAddress((void**)&bufB, g_bufB);
    cudaGetSymbolAddress((void**)&bufC, g_bufC);

    // ---- spectral norms (sequential reuse of g_t/g_s is stream-ordered) ----
    sn_tk<<<9, 256>>>(w1, u1, 256, 2304);
    sn_sk<<<256, 256>>>(w1, 2304);
    sn_fin<<<1, 256>>>(256, 2304, 0);

    sn_tk<<<9, 256>>>(w2, u2, 512, 2304);
    sn_sk<<<512, 256>>>(w2, 2304);
    sn_fin<<<1, 256>>>(512, 2304, 1);

    sn_tk<<<1, 256>>>(wsk, us, 512, 256);
    sn_sk<<<512, 256>>>(wsk, 256);
    sn_fin<<<1, 256>>>(512, 256, 2);

    // ---- skip-path blur: x -> bufB [16,256,63,63] ----
    {
        int total = 16 * 256 * 63 * 63;
        blur_kernel<<<(total + 255) / 256, 256>>>(x, bufB, 16 * 256, 64, 1, 63);
    }

    // ---- conv1: x -> bufA [16,256,64,64], bias+lrelu ----
    conv3x3_kernel<256, 4, 4, 64, 1, 1, 64, 64>
        <<<dim3(64, 4, 16), 256>>>(x, w1, b1, bufA, 256, 0, 64);

    // ---- blur: bufA -> bufC [16,256,65,65] ----
    {
        int total = 16 * 256 * 65 * 65;
        blur_kernel<<<(total + 255) / 256, 256>>>(bufA, bufC, 16 * 256, 64, 2, 65);
    }

    // ---- conv2: bufC -> d_out [16,512,32,32], bias+lrelu ----
    conv3x3_kernel<256, 8, 2, 32, 2, 0, 65, 65>
        <<<dim3(32, 4, 16), 256>>>(bufC, w2, b2, out, 512, 1, 32);

    // ---- skip 1x1 stride-2 + residual add + /sqrt(2) ----
    skip1x1_kernel<<<dim3(32, 4, 16), 256>>>(bufB, wsk, out);
}

// round 4
// speedup vs baseline: 4.9250x; 4.9250x over previous
#include <cuda_runtime.h>
#include <cuda_fp16.h>
#include <math.h>
#include <stdint.h>

#define RSQRT2 0.70710678118654752f

// ---------------- device scratch (allocation-free rule) ----------------
__device__ float g_inv_sigma[3];
__device__ float g_t[2304];
__device__ float g_s[512];
__device__ __half g_xpad[16 * 256 * 66 * 66];   // padded fp16 x (conv1 input)
__device__ __half g_bufA[16 * 256 * 64 * 64];   // conv1 output (fp16)
__device__ __half g_bufB[16 * 256 * 63 * 63];   // blur(x, pad=1) fp16
__device__ __half g_bufC[16 * 256 * 65 * 65];   // blur(conv1, pad=2) fp16
__device__ __half g_wt1[256 * 9 * 256];         // [oc][khw][ic] * 1/sigma
__device__ __half g_wt2[512 * 9 * 256];
__device__ __half g_wts[512 * 256];             // * 1/sigma * rsqrt2

// ---------------- helpers ----------------
__device__ __forceinline__ float warp_sum(float v) {
#pragma unroll
    for (int o = 16; o; o >>= 1) v += __shfl_down_sync(0xffffffffu, v, o);
    return v;
}

__device__ float block_sum(float v) {
    __shared__ float red[32];
    int lane = threadIdx.x & 31, w = threadIdx.x >> 5;
    v = warp_sum(v);
    if (lane == 0) red[w] = v;
    __syncthreads();
    float r = 0.f;
    if (w == 0) {
        int nw = (blockDim.x + 31) >> 5;
        r = (lane < nw) ? red[lane] : 0.f;
        r = warp_sum(r);
    }
    __syncthreads();
    return r;
}

__device__ __forceinline__ uint32_t smem_u32(const void* p) {
    uint32_t a;
    asm("{ .reg .u64 t; cvta.to.shared.u64 t, %1; cvt.u32.u64 %0, t; }" : "=r"(a) : "l"(p));
    return a;
}

__device__ __forceinline__ void sts32u(uint32_t a, uint32_t v) {
    asm volatile("st.shared.b32 [%0], %1;" :: "r"(a), "r"(v) : "memory");
}
__device__ __forceinline__ void sts32f(uint32_t a, float v) {
    asm volatile("st.shared.b32 [%0], %1;" :: "r"(a), "f"(v) : "memory");
}
__device__ __forceinline__ void sts128(uint32_t a, int4 v) {
    asm volatile("st.shared.v4.b32 [%0], {%1,%2,%3,%4};"
                 :: "r"(a), "r"(v.x), "r"(v.y), "r"(v.z), "r"(v.w) : "memory");
}
__device__ __forceinline__ float4 lds128f(uint32_t a) {
    float4 v;
    asm volatile("ld.shared.v4.f32 {%0,%1,%2,%3}, [%4];"
                 : "=f"(v.x), "=f"(v.y), "=f"(v.z), "=f"(v.w) : "r"(a));
    return v;
}

// trans (for A: smem [k][m], fragment becomes [m][k])
__device__ __forceinline__ void ldsm4t(uint32_t* r, uint32_t addr) {
    asm volatile("ldmatrix.sync.aligned.m8n8.x4.trans.shared.b16 {%0,%1,%2,%3}, [%4];"
                 : "=r"(r[0]), "=r"(r[1]), "=r"(r[2]), "=r"(r[3]) : "r"(addr));
}
// non-trans (for B: smem [n][k], fragment lane -> n=lane/4, k=(lane%4)*2+{0,1})
__device__ __forceinline__ void ldsm4(uint32_t* r, uint32_t addr) {
    asm volatile("ldmatrix.sync.aligned.m8n8.x4.shared.b16 {%0,%1,%2,%3}, [%4];"
                 : "=r"(r[0]), "=r"(r[1]), "=r"(r[2]), "=r"(r[3]) : "r"(addr));
}

__device__ __forceinline__ void mma16816(float* c, const uint32_t* a, const uint32_t* b) {
    asm volatile(
        "mma.sync.aligned.m16n8k16.row.col.f32.f16.f16.f32 "
        "{%0,%1,%2,%3}, {%4,%5,%6,%7}, {%8,%9}, {%0,%1,%2,%3};"
        : "+f"(c[0]), "+f"(c[1]), "+f"(c[2]), "+f"(c[3])
        : "r"(a[0]), "r"(a[1]), "r"(a[2]), "r"(a[3]), "r"(b[0]), "r"(b[1]));
}

// ---------------- spectral norm ----------------
__global__ void sn_tk(const float* __restrict__ W, const float* __restrict__ u,
                      int H, int K) {
    __shared__ float us[512];
    for (int i = threadIdx.x; i < H; i += blockDim.x) us[i] = u[i];
    __syncthreads();
    int j = blockIdx.x * blockDim.x + threadIdx.x;
    if (j >= K) return;
    float s = 0.f;
    for (int i = 0; i < H; i++) s = fmaf(W[(size_t)i * K + j], us[i], s);
    g_t[j] = s;
}

__global__ void sn_sk(const float* __restrict__ W, int K) {
    int i = blockIdx.x;
    float s = 0.f;
    for (int j = threadIdx.x; j < K; j += blockDim.x)
        s = fmaf(W[(size_t)i * K + j], g_t[j], s);
    s = block_sum(s);
    if (threadIdx.x == 0) g_s[i] = s;
}

__global__ void sn_fin(int H, int K, int idx) {
    float a = 0.f;
    for (int j = threadIdx.x; j < K; j += blockDim.x) {
        float t = g_t[j];
        a = fmaf(t, t, a);
    }
    float aT = block_sum(a);
    float b = 0.f;
    for (int i = threadIdx.x; i < H; i += blockDim.x) {
        float t = g_s[i];
        b = fmaf(t, t, b);
    }
    float bT = block_sum(b);
    if (threadIdx.x == 0) {
        float nt = sqrtf(aT);
        float nwt = sqrtf(bT);
        float nwv = nwt / (nt + 1e-12f);
        float sigma = nwv * nwv / (nwv + 1e-12f);
        g_inv_sigma[idx] = 1.f / sigma;
    }
}

// wt[oc][khw][ic] = w[oc][ic][khw] * inv_sigma * extra  (fp16)
__global__ void prep_w(const float* __restrict__ w, __half* __restrict__ wt,
                       int OC, int IC, int KHW, int sigIdx, float extra) {
    int idx = blockIdx.x * blockDim.x + threadIdx.x;
    int total = OC * IC * KHW;
    if (idx >= total) return;
    int khw = idx % KHW;
    int t = idx / KHW;
    int ic = t % IC;
    int oc = t / IC;
    float v = w[idx] * g_inv_sigma[sigIdx] * extra;
    wt[((size_t)oc * KHW + khw) * IC + ic] = __float2half_rn(v);
}

// x f32 [16,256,64,64] -> xpad fp16 [16,256,66,66] with zero halo
__global__ void pad_x(const float* __restrict__ x, __half* __restrict__ xp) {
    int idx = blockIdx.x * blockDim.x + threadIdx.x;
    const int total = 16 * 256 * 66 * 66;
    if (idx >= total) return;
    int c = idx % 66;
    int t = idx / 66;
    int r = t % 66;
    int p = t / 66;
    float v = 0.f;
    if (r >= 1 && r <= 64 && c >= 1 && c <= 64)
        v = x[((size_t)p * 64 + (r - 1)) * 64 + (c - 1)];
    xp[idx] = __float2half_rn(v);
}

// ---------------- 4x4 binomial blur -> fp16 ----------------
template <typename Tin>
__global__ void blur_h(const Tin* __restrict__ in, __half* __restrict__ out,
                       int NC, int IHW, int P, int OHW) {
    int idx = blockIdx.x * blockDim.x + threadIdx.x;
    int total = NC * OHW * OHW;
    if (idx >= total) return;
    int x = idx % OHW;
    int t = idx / OHW;
    int y = t % OHW;
    int nc = t / OHW;
    const Tin* ip = in + (size_t)nc * IHW * IHW;
    const float kv[4] = {1.f, 3.f, 3.f, 1.f};
    float s = 0.f;
#pragma unroll
    for (int i = 0; i < 4; i++) {
        int yy = y + i - P;
        if ((unsigned)yy >= (unsigned)IHW) continue;
#pragma unroll
        for (int j = 0; j < 4; j++) {
            int xx = x + j - P;
            if ((unsigned)xx >= (unsigned)IHW) continue;
            s = fmaf(kv[i] * kv[j], (float)ip[(size_t)yy * IHW + xx], s);
        }
    }
    out[idx] = __float2half_rn(s * (1.f / 64.f));
}

// ---------------------------------------------------------------------------
// fp16 mma.sync implicit-GEMM conv. Block tile M=128 (pixels) x N=128 (oc),
// K staged by 32. A smem transposed [k32][m128] pitch 272B; B smem [n128][k32]
// pitch 80B. A via ldmatrix.trans, B via ldmatrix (non-trans).
// 8 warps each compute 32m x 64n.
// EPI: 0 = bias+lrelu -> fp16, 1 = bias+lrelu -> f32, 2 = out*rsqrt2 + acc -> f32
// Inputs are pre-padded: every (ih,iw) access is in-range by construction.
// ---------------------------------------------------------------------------
#define CONV_SMEM 37888

template <int KHW, int STRIDE, int EPI>
__global__ void __launch_bounds__(256, 2) conv_hmma(
    const __half* __restrict__ in, const __half* __restrict__ wt,
    const float* __restrict__ bias, void* __restrict__ outv,
    int IC, int IH, int IW, int OC, int OH, int OW, int NS) {
    extern __shared__ char smem[];
    const uint32_t sb = smem_u32(smem);
    const uint32_t aOff0 = 0, aOff1 = 8704;
    const uint32_t bOff0 = 17408, bOff1 = 27648;

    const int tid = threadIdx.x;
    const int lane = tid & 31;
    const int wid = tid >> 5;
    const int wm = wid & 3;
    const int wn = wid >> 2;

    const int m0 = blockIdx.x * 128;
    const int ocb = blockIdx.y * 128;
    const int ohw = OH * OW;
    const int img = m0 / ohw;
    const int rbase = m0 - img * ohw;

    // A-ldg mapping: thread -> (pixel pair, 8 input channels)
    const int mp = (tid & 63) * 2;
    const int icg = tid >> 6;
    const int rr = rbase + mp;
    const int oh = rr / OW;
    const int ow = rr - oh * OW;
    const size_t chs = (size_t)IH * IW;
    const __half* inb = in + (size_t)img * IC * chs +
                        (size_t)(oh * STRIDE) * IW + ow * STRIDE;

    // ldmatrix lane addresses
    const int lg = lane >> 3, lr = lane & 7;
    const uint32_t aLM = sb + (uint32_t)((lr + ((lg >> 1) << 3)) * 272 +
                                         wm * 64 + ((lg & 1) << 4));
    const uint32_t bLM = sb + (uint32_t)((lr + ((lg >> 1) << 3)) * 80 +
                                         ((lg & 1) << 4) + wn * 5120);

    float c[2][8][4];
#pragma unroll
    for (int mb = 0; mb < 2; mb++)
#pragma unroll
        for (int nb = 0; nb < 8; nb++)
#pragma unroll
            for (int q = 0; q < 4; q++) c[mb][nb][q] = 0.f;

    uint32_t ra[8];
    int4 rb[2];

    auto LDG = [&](int s) {
        const int kk = s * 32;
        const int khw = (KHW == 1) ? 0 : (kk >> 8);
        const int ic0 = kk - (khw << 8);
        int kh = 0, kw = 0;
        if (KHW == 9) { kh = khw / 3; kw = khw - kh * 3; }
        const __half* ap = inb + (size_t)(ic0 + icg * 8) * chs + (size_t)kh * IW + kw;
#pragma unroll
        for (int p = 0; p < 8; p++) {
            const __half* q = ap + (size_t)p * chs;
            __half2 h = __halves2half2(__ldg(q), __ldg(q + STRIDE));
            ra[p] = *reinterpret_cast<uint32_t*>(&h);
        }
#pragma unroll
        for (int i = 0; i < 2; i++) {
            int idx = i * 256 + tid;
            int oc = idx >> 2, qq = idx & 3;
            rb[i] = *reinterpret_cast<const int4*>(
                wt + ((size_t)(ocb + oc) * KHW + khw) * IC + ic0 + qq * 8);
        }
    };

    auto STS = [&](uint32_t aB, uint32_t bB) {
#pragma unroll
        for (int p = 0; p < 8; p++)
            sts32u(aB + (uint32_t)((icg * 8 + p) * 272 + mp * 2), ra[p]);
#pragma unroll
        for (int i = 0; i < 2; i++) {
            int idx = i * 256 + tid;
            int oc = idx >> 2, qq = idx & 3;
            sts128(bB + (uint32_t)(oc * 80 + qq * 16), rb[i]);
        }
    };

    auto MMA = [&](uint32_t aOff, uint32_t bOff) {
#pragma unroll
        for (int k16 = 0; k16 < 2; k16++) {
            uint32_t a[2][4], b[8][2];
#pragma unroll
            for (int mb = 0; mb < 2; mb++)
                ldsm4t(a[mb], aLM + aOff + k16 * 4352 + mb * 32);
#pragma unroll
            for (int nbp = 0; nbp < 4; nbp++) {
                uint32_t r[4];
                ldsm4(r, bLM + bOff + k16 * 32 + nbp * 1280);
                b[nbp * 2][0] = r[0]; b[nbp * 2][1] = r[1];
                b[nbp * 2 + 1][0] = r[2]; b[nbp * 2 + 1][1] = r[3];
            }
#pragma unroll
            for (int mb = 0; mb < 2; mb++)
#pragma unroll
                for (int nb = 0; nb < 8; nb++)
                    mma16816(c[mb][nb], a[mb], b[nb]);
        }
    };

    // pipeline: ldg(0); sts(0); ldg(1); sync; loop
    LDG(0);
    STS(sb + aOff0, sb + bOff0);
    if (NS > 1) LDG(1);
    __syncthreads();

    for (int s = 0; s < NS; s++) {
        const int b = s & 1;
        MMA(b ? aOff1 : aOff0, b ? bOff1 : bOff0);
        if (s + 1 < NS) STS(sb + (b ? aOff0 : aOff1), sb + (b ? bOff0 : bOff1));
        __syncthreads();
        if (s + 2 < NS) LDG(s + 2);
    }

    // ---- epilogue: transpose via smem, coalesced stores ----
    const int erow = lane >> 2;
    const int ecolp = (lane & 3) * 2;

    for (int nc = 0; nc < 4; nc++) {
        if (wn == (nc >> 1)) {
            const int nbBase = (nc & 1) * 4;
#pragma unroll
            for (int mb = 0; mb < 2; mb++) {
                const int mrow = wm * 32 + mb * 16 + erow;
#pragma unroll
                for (int j = 0; j < 4; j++) {
                    const int nb = nbBase + j;
                    const int ocl = j * 8 + ecolp;
                    const float* cc = c[mb][nb];
                    sts32f(sb + (uint32_t)(ocl * 544 + mrow * 4), cc[0]);
                    sts32f(sb + (uint32_t)((ocl + 1) * 544 + mrow * 4), cc[1]);
                    sts32f(sb + (uint32_t)(ocl * 544 + (mrow + 8) * 4), cc[2]);
                    sts32f(sb + (uint32_t)((ocl + 1) * 544 + (mrow + 8) * 4), cc[3]);
                }
            }
        }
        __syncthreads();
#pragma unroll
        for (int p = 0; p < 4; p++) {
            const int idx = p * 256 + tid;
            const int ocl = idx >> 5;
            const int mq = (idx & 31) * 4;
            float4 v = lds128f(sb + (uint32_t)(ocl * 544 + mq * 4));
            const int oc = ocb + nc * 32 + ocl;
            const size_t go = ((size_t)img * OC + oc) * ohw + rbase + mq;
            if (EPI == 0) {
                const float bv = __ldg(bias + oc);
                v.x += bv; v.y += bv; v.z += bv; v.w += bv;
                v.x = v.x > 0.f ? v.x : 0.2f * v.x;
                v.y = v.y > 0.f ? v.y : 0.2f * v.y;
                v.z = v.z > 0.f ? v.z : 0.2f * v.z;
                v.w = v.w > 0.f ? v.w : 0.2f * v.w;
                __half2 h0 = __floats2half2_rn(v.x, v.y);
                __half2 h1 = __floats2half2_rn(v.z, v.w);
                uint2 u;
                u.x = *reinterpret_cast<uint32_t*>(&h0);
                u.y = *reinterpret_cast<uint32_t*>(&h1);
                *reinterpret_cast<uint2*>((__half*)outv + go) = u;
            } else if (EPI == 1) {
                const float bv = __ldg(bias + oc);
                v.x += bv; v.y += bv; v.z += bv; v.w += bv;
                v.x = v.x > 0.f ? v.x : 0.2f * v.x;
                v.y = v.y > 0.f ? v.y : 0.2f * v.y;
                v.z = v.z > 0.f ? v.z : 0.2f * v.z;
                v.w = v.w > 0.f ? v.w : 0.2f * v.w;
                *reinterpret_cast<float4*>((float*)outv + go) = v;
            } else {
                float* op = (float*)outv + go;
                float4 o = *reinterpret_cast<const float4*>(op);
                o.x = o.x * RSQRT2 + v.x;
                o.y = o.y * RSQRT2 + v.y;
                o.z = o.z * RSQRT2 + v.z;
                o.w = o.w * RSQRT2 + v.w;
                *reinterpret_cast<float4*>(op) = o;
            }
        }
        __syncthreads();
    }
}

// ---------------------------------------------------------------------------
extern "C" void kernel_launch(void* const* d_in, const int* in_sizes, int n_in,
                              void* d_out, int out_size) {
    const float* x   = (const float*)d_in[0];
    const float* w1  = (const float*)d_in[1];
    const float* u1  = (const float*)d_in[2];
    const float* b1  = (const float*)d_in[4];
    const float* w2  = (const float*)d_in[5];
    const float* u2  = (const float*)d_in[6];
    const float* b2  = (const float*)d_in[8];
    const float* wsk = (const float*)d_in[9];
    const float* us  = (const float*)d_in[10];
    float* out = (float*)d_out;

    __half *xpad, *bufA, *bufB, *bufC, *wt1, *wt2, *wts;
    cudaGetSymbolAddress((void**)&xpad, g_xpad);
    cudaGetSymbolAddress((void**)&bufA, g_bufA);
    cudaGetSymbolAddress((void**)&bufB, g_bufB);
    cudaGetSymbolAddress((void**)&bufC, g_bufC);
    cudaGetSymbolAddress((void**)&wt1, g_wt1);
    cudaGetSymbolAddress((void**)&wt2, g_wt2);
    cudaGetSymbolAddress((void**)&wts, g_wts);

    // ---- spectral norms ----
    sn_tk<<<9, 256>>>(w1, u1, 256, 2304);
    sn_sk<<<256, 256>>>(w1, 2304);
    sn_fin<<<1, 256>>>(256, 2304, 0);

    sn_tk<<<9, 256>>>(w2, u2, 512, 2304);
    sn_sk<<<512, 256>>>(w2, 2304);
    sn_fin<<<1, 256>>>(512, 2304, 1);

    sn_tk<<<1, 256>>>(wsk, us, 512, 256);
    sn_sk<<<512, 256>>>(wsk, 256);
    sn_fin<<<1, 256>>>(512, 256, 2);

    // ---- weight prep (fp16, transposed, scale-folded) ----
    prep_w<<<(256 * 256 * 9 + 255) / 256, 256>>>(w1, wt1, 256, 256, 9, 0, 1.f);
    prep_w<<<(512 * 256 * 9 + 255) / 256, 256>>>(w2, wt2, 512, 256, 9, 1, 1.f);
    prep_w<<<(512 * 256 + 255) / 256, 256>>>(wsk, wts, 512, 256, 1, 2, RSQRT2);

    // ---- input prep ----
    {
        const int t1 = 16 * 256 * 66 * 66;
        pad_x<<<(t1 + 255) / 256, 256>>>(x, xpad);
        const int t2 = 16 * 256 * 63 * 63;
        blur_h<float><<<(t2 + 255) / 256, 256>>>(x, bufB, 16 * 256, 64, 1, 63);
    }

    // ---- conv1: xpad -> bufA fp16 [16,256,64,64], bias+lrelu ----
    conv_hmma<9, 1, 0><<<dim3(512, 2), 256, CONV_SMEM>>>(
        xpad, wt1, b1, bufA, 256, 66, 66, 256, 64, 64, 72);

    // ---- blur: bufA -> bufC fp16 [16,256,65,65] ----
    {
        const int t = 16 * 256 * 65 * 65;
        blur_h<__half><<<(t + 255) / 256, 256>>>(bufA, bufC, 16 * 256, 64, 2, 65);
    }

    // ---- conv2: bufC -> d_out f32 [16,512,32,32], bias+lrelu ----
    conv_hmma<9, 2, 1><<<dim3(128, 4), 256, CONV_SMEM>>>(
        bufC, wt2, b2, out, 256, 65, 65, 512, 32, 32, 72);

    // ---- skip: 1x1 s2 on bufB, out = out*rsqrt2 + acc (rsqrt2 in weights) ----
    conv_hmma<1, 2, 2><<<dim3(128, 4), 256, CONV_SMEM>>>(
        bufB, wts, nullptr, out, 256, 63, 63, 512, 32, 32, 8);
}

// round 5
// speedup vs baseline: 5.4846x; 1.1136x over previous
#include <cuda_runtime.h>
#include <cuda_fp16.h>
#include <math.h>
#include <stdint.h>

#define RSQRT2 0.70710678118654752f

// ---------------- device scratch (allocation-free rule) ----------------
__device__ float g_t1[2304];
__device__ float g_t2[2304];
__device__ float g_t3[256];
__device__ float g_nt2[3];   // ||t||^2 per weight
__device__ float g_ns2[3];   // ||W t||^2 per weight
__device__ __half g_xpad[16 * 256 * 66 * 66];   // padded fp16 x (conv1 input)
__device__ __half g_bufA[16 * 256 * 64 * 64];   // conv1 output (fp16)
__device__ __half g_bufB[16 * 256 * 63 * 63];   // blur(x, pad=1) fp16
__device__ __half g_bufC[16 * 256 * 65 * 65];   // blur(conv1, pad=2) fp16
__device__ __half g_wt1[256 * 9 * 256];         // [oc][khw][ic] * 1/sigma
__device__ __half g_wt2[512 * 9 * 256];
__device__ __half g_wts[512 * 256];             // * 1/sigma * rsqrt2

// ---------------- helpers ----------------
__device__ __forceinline__ float warp_sum(float v) {
#pragma unroll
    for (int o = 16; o; o >>= 1) v += __shfl_down_sync(0xffffffffu, v, o);
    return v;
}

__device__ float block_sum(float v) {
    __shared__ float red[32];
    int lane = threadIdx.x & 31, w = threadIdx.x >> 5;
    v = warp_sum(v);
    if (lane == 0) red[w] = v;
    __syncthreads();
    float r = 0.f;
    if (w == 0) {
        int nw = (blockDim.x + 31) >> 5;
        r = (lane < nw) ? red[lane] : 0.f;
        r = warp_sum(r);
    }
    __syncthreads();
    return r;
}

__device__ __forceinline__ uint32_t smem_u32(const void* p) {
    uint32_t a;
    asm("{ .reg .u64 t; cvta.to.shared.u64 t, %1; cvt.u32.u64 %0, t; }" : "=r"(a) : "l"(p));
    return a;
}

__device__ __forceinline__ void sts32u(uint32_t a, uint32_t v) {
    asm volatile("st.shared.b32 [%0], %1;" :: "r"(a), "r"(v) : "memory");
}
__device__ __forceinline__ void sts32f(uint32_t a, float v) {
    asm volatile("st.shared.b32 [%0], %1;" :: "r"(a), "f"(v) : "memory");
}
__device__ __forceinline__ void sts128(uint32_t a, int4 v) {
    asm volatile("st.shared.v4.b32 [%0], {%1,%2,%3,%4};"
                 :: "r"(a), "r"(v.x), "r"(v.y), "r"(v.z), "r"(v.w) : "memory");
}
__device__ __forceinline__ float4 lds128f(uint32_t a) {
    float4 v;
    asm volatile("ld.shared.v4.f32 {%0,%1,%2,%3}, [%4];"
                 : "=f"(v.x), "=f"(v.y), "=f"(v.z), "=f"(v.w) : "r"(a));
    return v;
}

// trans (for A: smem [k][m], fragment becomes [m][k])
__device__ __forceinline__ void ldsm4t(uint32_t* r, uint32_t addr) {
    asm volatile("ldmatrix.sync.aligned.m8n8.x4.trans.shared.b16 {%0,%1,%2,%3}, [%4];"
                 : "=r"(r[0]), "=r"(r[1]), "=r"(r[2]), "=r"(r[3]) : "r"(addr));
}
// non-trans (for B: smem [n][k])
__device__ __forceinline__ void ldsm4(uint32_t* r, uint32_t addr) {
    asm volatile("ldmatrix.sync.aligned.m8n8.x4.shared.b16 {%0,%1,%2,%3}, [%4];"
                 : "=r"(r[0]), "=r"(r[1]), "=r"(r[2]), "=r"(r[3]) : "r"(addr));
}

__device__ __forceinline__ void mma16816(float* c, const uint32_t* a, const uint32_t* b) {
    asm volatile(
        "mma.sync.aligned.m16n8k16.row.col.f32.f16.f16.f32 "
        "{%0,%1,%2,%3}, {%4,%5,%6,%7}, {%8,%9}, {%0,%1,%2,%3};"
        : "+f"(c[0]), "+f"(c[1]), "+f"(c[2]), "+f"(c[3])
        : "r"(a[0]), "r"(a[1]), "r"(a[2]), "r"(a[3]), "r"(b[0]), "r"(b[1]));
}

// ---------------- spectral norm (wide) ----------------
__global__ void sn_zero() {
    int t = threadIdx.x;
    for (int i = t; i < 2304; i += 256) { g_t1[i] = 0.f; g_t2[i] = 0.f; }
    if (t < 256) g_t3[t] = 0.f;
    if (t < 3) { g_nt2[t] = 0.f; g_ns2[t] = 0.f; }
}

// t[j] += sum_{i in chunk} W[i*K+j]*u[i];  grid = (ceil(K/256), 8)
__global__ void sn_tk_w(const float* __restrict__ W, const float* __restrict__ u,
                        float* __restrict__ t, int H, int K) {
    int j = blockIdx.x * 256 + threadIdx.x;
    if (j >= K) return;
    int chunk = (H + 7) / 8;
    int i0 = blockIdx.y * chunk;
    int i1 = min(i0 + chunk, H);
    float s = 0.f;
    for (int i = i0; i < i1; i++)
        s = fmaf(W[(size_t)i * K + j], __ldg(u + i), s);
    atomicAdd(t + j, s);
}

// per row i: s = W[i,:].t ; atomicAdd(ns2, s^2). block 0 also sums ||t||^2.
__global__ void sn_sk_w(const float* __restrict__ W, const float* __restrict__ t,
                        int K, int idx) {
    int i = blockIdx.x;
    float s = 0.f;
    for (int j = threadIdx.x; j < K; j += blockDim.x)
        s = fmaf(W[(size_t)i * K + j], __ldg(t + j), s);
    s = block_sum(s);
    if (threadIdx.x == 0) atomicAdd(&g_ns2[idx], s * s);
    if (i == 0) {
        float a = 0.f;
        for (int j = threadIdx.x; j < K; j += blockDim.x) {
            float tv = __ldg(t + j);
            a = fmaf(tv, tv, a);
        }
        a = block_sum(a);
        if (threadIdx.x == 0) atomicAdd(&g_nt2[idx], a);
    }
}

// wt[oc][khw][ic] = w[oc][ic][khw] * inv_sigma * extra (fp16); sigma inline
__global__ void prep_w(const float* __restrict__ w, __half* __restrict__ wt,
                       int OC, int IC, int KHW, int sigIdx, float extra) {
    int idx = blockIdx.x * blockDim.x + threadIdx.x;
    int total = OC * IC * KHW;
    if (idx >= total) return;
    float nt = sqrtf(g_nt2[sigIdx]);
    float nwt = sqrtf(g_ns2[sigIdx]);
    float nwv = nwt / (nt + 1e-12f);
    float sigma = nwv * nwv / (nwv + 1e-12f);
    int khw = idx % KHW;
    int t = idx / KHW;
    int ic = t % IC;
    int oc = t / IC;
    float v = w[idx] * (extra / sigma);
    wt[((size_t)oc * KHW + khw) * IC + ic] = __float2half_rn(v);
}

// x f32 [16,256,64,64] -> xpad fp16 [16,256,66,66] with zero halo
__global__ void pad_x(const float* __restrict__ x, __half* __restrict__ xp) {
    int idx = blockIdx.x * blockDim.x + threadIdx.x;
    const int total = 16 * 256 * 66 * 66;
    if (idx >= total) return;
    int c = idx % 66;
    int t = idx / 66;
    int r = t % 66;
    int p = t / 66;
    float v = 0.f;
    if (r >= 1 && r <= 64 && c >= 1 && c <= 64)
        v = x[((size_t)p * 64 + (r - 1)) * 64 + (c - 1)];
    xp[idx] = __float2half_rn(v);
}

// ---------------- 4x4 binomial blur -> fp16 ----------------
template <typename Tin>
__global__ void blur_h(const Tin* __restrict__ in, __half* __restrict__ out,
                       int NC, int IHW, int P, int OHW) {
    int idx = blockIdx.x * blockDim.x + threadIdx.x;
    int total = NC * OHW * OHW;
    if (idx >= total) return;
    int x = idx % OHW;
    int t = idx / OHW;
    int y = t % OHW;
    int nc = t / OHW;
    const Tin* ip = in + (size_t)nc * IHW * IHW;
    const float kv[4] = {1.f, 3.f, 3.f, 1.f};
    float s = 0.f;
#pragma unroll
    for (int i = 0; i < 4; i++) {
        int yy = y + i - P;
        if ((unsigned)yy >= (unsigned)IHW) continue;
#pragma unroll
        for (int j = 0; j < 4; j++) {
            int xx = x + j - P;
            if ((unsigned)xx >= (unsigned)IHW) continue;
            s = fmaf(kv[i] * kv[j], (float)ip[(size_t)yy * IHW + xx], s);
        }
    }
    out[idx] = __float2half_rn(s * (1.f / 64.f));
}

// ---------------------------------------------------------------------------
// fp16 mma.sync implicit-GEMM conv. Block tile M=128 (pixels) x N=128 (oc),
// K staged by 32. A smem [k32][m128] pitch 272B (ldmatrix.trans);
// B smem [n128][k32] pitch 80B (ldmatrix). 8 warps, each 32m x 64n.
// EPI: 0 = bias+lrelu -> fp16, 1 = bias+lrelu -> f32, 2 = out*rsqrt2+acc -> f32
// ---------------------------------------------------------------------------
#define CONV_SMEM 37888

template <int KHW, int STRIDE, int EPI>
__global__ void __launch_bounds__(256, 2) conv_hmma(
    const __half* __restrict__ in, const __half* __restrict__ wt,
    const float* __restrict__ bias, void* __restrict__ outv,
    int IC, int IH, int IW, int OC, int OH, int OW, int NS) {
    extern __shared__ char smem[];
    const uint32_t sb = smem_u32(smem);
    const uint32_t aOff0 = 0, aOff1 = 8704;
    const uint32_t bOff0 = 17408, bOff1 = 27648;

    const int tid = threadIdx.x;
    const int lane = tid & 31;
    const int wid = tid >> 5;
    const int wm = wid & 3;
    const int wn = wid >> 2;

    const int m0 = blockIdx.x * 128;
    const int ocb = blockIdx.y * 128;
    const int ohw = OH * OW;
    const int img = m0 / ohw;
    const int rbase = m0 - img * ohw;

    const int mp = (tid & 63) * 2;
    const int icg = tid >> 6;
    const int rr = rbase + mp;
    const int oh = rr / OW;
    const int ow = rr - oh * OW;
    const size_t chs = (size_t)IH * IW;
    const __half* inb = in + (size_t)img * IC * chs +
                        (size_t)(oh * STRIDE) * IW + ow * STRIDE;

    const int lg = lane >> 3, lr = lane & 7;
    const uint32_t aLM = sb + (uint32_t)((lr + ((lg >> 1) << 3)) * 272 +
                                         wm * 64 + ((lg & 1) << 4));
    const uint32_t bLM = sb + (uint32_t)((lr + ((lg >> 1) << 3)) * 80 +
                                         ((lg & 1) << 4) + wn * 5120);

    float c[2][8][4];
#pragma unroll
    for (int mb = 0; mb < 2; mb++)
#pragma unroll
        for (int nb = 0; nb < 8; nb++)
#pragma unroll
            for (int q = 0; q < 4; q++) c[mb][nb][q] = 0.f;

    uint32_t ra[8];
    int4 rb[2];

    auto LDG = [&](int s) {
        const int kk = s * 32;
        const int khw = (KHW == 1) ? 0 : (kk >> 8);
        const int ic0 = kk - (khw << 8);
        int kh = 0, kw = 0;
        if (KHW == 9) { kh = khw / 3; kw = khw - kh * 3; }
        const __half* ap = inb + (size_t)(ic0 + icg * 8) * chs + (size_t)kh * IW + kw;
#pragma unroll
        for (int p = 0; p < 8; p++) {
            const __half* q = ap + (size_t)p * chs;
            __half2 h = __halves2half2(__ldg(q), __ldg(q + STRIDE));
            ra[p] = *reinterpret_cast<uint32_t*>(&h);
        }
#pragma unroll
        for (int i = 0; i < 2; i++) {
            int idx = i * 256 + tid;
            int oc = idx >> 2, qq = idx & 3;
            rb[i] = *reinterpret_cast<const int4*>(
                wt + ((size_t)(ocb + oc) * KHW + khw) * IC + ic0 + qq * 8);
        }
    };

    auto STS = [&](uint32_t aB, uint32_t bB) {
#pragma unroll
        for (int p = 0; p < 8; p++)
            sts32u(aB + (uint32_t)((icg * 8 + p) * 272 + mp * 2), ra[p]);
#pragma unroll
        for (int i = 0; i < 2; i++) {
            int idx = i * 256 + tid;
            int oc = idx >> 2, qq = idx & 3;
            sts128(bB + (uint32_t)(oc * 80 + qq * 16), rb[i]);
        }
    };

    auto MMA = [&](uint32_t aOff, uint32_t bOff) {
#pragma unroll
        for (int k16 = 0; k16 < 2; k16++) {
            uint32_t a[2][4], b[8][2];
#pragma unroll
            for (int mb = 0; mb < 2; mb++)
                ldsm4t(a[mb], aLM + aOff + k16 * 4352 + mb * 32);
#pragma unroll
            for (int nbp = 0; nbp < 4; nbp++) {
                uint32_t r[4];
                ldsm4(r, bLM + bOff + k16 * 32 + nbp * 1280);
                b[nbp * 2][0] = r[0]; b[nbp * 2][1] = r[1];
                b[nbp * 2 + 1][0] = r[2]; b[nbp * 2 + 1][1] = r[3];
            }
#pragma unroll
            for (int mb = 0; mb < 2; mb++)
#pragma unroll
                for (int nb = 0; nb < 8; nb++)
                    mma16816(c[mb][nb], a[mb], b[nb]);
        }
    };

    LDG(0);
    STS(sb + aOff0, sb + bOff0);
    if (NS > 1) LDG(1);
    __syncthreads();

    for (int s = 0; s < NS; s++) {
        const int b = s & 1;
        MMA(b ? aOff1 : aOff0, b ? bOff1 : bOff0);
        if (s + 1 < NS) STS(sb + (b ? aOff0 : aOff1), sb + (b ? bOff0 : bOff1));
        __syncthreads();
        if (s + 2 < NS) LDG(s + 2);
    }

    // ---- epilogue ----
    const int erow = lane >> 2;
    const int ecolp = (lane & 3) * 2;

    for (int nc = 0; nc < 4; nc++) {
        if (wn == (nc >> 1)) {
            const int nbBase = (nc & 1) * 4;
#pragma unroll
            for (int mb = 0; mb < 2; mb++) {
                const int mrow = wm * 32 + mb * 16 + erow;
#pragma unroll
                for (int j = 0; j < 4; j++) {
                    const int nb = nbBase + j;
                    const int ocl = j * 8 + ecolp;
                    const float* cc = c[mb][nb];
                    sts32f(sb + (uint32_t)(ocl * 544 + mrow * 4), cc[0]);
                    sts32f(sb + (uint32_t)((ocl + 1) * 544 + mrow * 4), cc[1]);
                    sts32f(sb + (uint32_t)(ocl * 544 + (mrow + 8) * 4), cc[2]);
                    sts32f(sb + (uint32_t)((ocl + 1) * 544 + (mrow + 8) * 4), cc[3]);
                }
            }
        }
        __syncthreads();
#pragma unroll
        for (int p = 0; p < 4; p++) {
            const int idx = p * 256 + tid;
            const int ocl = idx >> 5;
            const int mq = (idx & 31) * 4;
            float4 v = lds128f(sb + (uint32_t)(ocl * 544 + mq * 4));
            const int oc = ocb + nc * 32 + ocl;
            const size_t go = ((size_t)img * OC + oc) * ohw + rbase + mq;
            if (EPI == 0) {
                const float bv = __ldg(bias + oc);
                v.x += bv; v.y += bv; v.z += bv; v.w += bv;
                v.x = v.x > 0.f ? v.x : 0.2f * v.x;
                v.y = v.y > 0.f ? v.y : 0.2f * v.y;
                v.z = v.z > 0.f ? v.z : 0.2f * v.z;
                v.w = v.w > 0.f ? v.w : 0.2f * v.w;
                __half2 h0 = __floats2half2_rn(v.x, v.y);
                __half2 h1 = __floats2half2_rn(v.z, v.w);
                uint2 u;
                u.x = *reinterpret_cast<uint32_t*>(&h0);
                u.y = *reinterpret_cast<uint32_t*>(&h1);
                *reinterpret_cast<uint2*>((__half*)outv + go) = u;
            } else if (EPI == 1) {
                const float bv = __ldg(bias + oc);
                v.x += bv; v.y += bv; v.z += bv; v.w += bv;
                v.x = v.x > 0.f ? v.x : 0.2f * v.x;
                v.y = v.y > 0.f ? v.y : 0.2f * v.y;
                v.z = v.z > 0.f ? v.z : 0.2f * v.z;
                v.w = v.w > 0.f ? v.w : 0.2f * v.w;
                *reinterpret_cast<float4*>((float*)outv + go) = v;
            } else {
                float* op = (float*)outv + go;
                float4 o = *reinterpret_cast<const float4*>(op);
                o.x = o.x * RSQRT2 + v.x;
                o.y = o.y * RSQRT2 + v.y;
                o.z = o.z * RSQRT2 + v.z;
                o.w = o.w * RSQRT2 + v.w;
                *reinterpret_cast<float4*>(op) = o;
            }
        }
        __syncthreads();
    }
}

// ---------------------------------------------------------------------------
extern "C" void kernel_launch(void* const* d_in, const int* in_sizes, int n_in,
                              void* d_out, int out_size) {
    const float* x   = (const float*)d_in[0];
    const float* w1  = (const float*)d_in[1];
    const float* u1  = (const float*)d_in[2];
    const float* b1  = (const float*)d_in[4];
    const float* w2  = (const float*)d_in[5];
    const float* u2  = (const float*)d_in[6];
    const float* b2  = (const float*)d_in[8];
    const float* wsk = (const float*)d_in[9];
    const float* us  = (const float*)d_in[10];
    float* out = (float*)d_out;

    __half *xpad, *bufA, *bufB, *bufC, *wt1, *wt2, *wts;
    float *t1, *t2, *t3;
    cudaGetSymbolAddress((void**)&xpad, g_xpad);
    cudaGetSymbolAddress((void**)&bufA, g_bufA);
    cudaGetSymbolAddress((void**)&bufB, g_bufB);
    cudaGetSymbolAddress((void**)&bufC, g_bufC);
    cudaGetSymbolAddress((void**)&wt1, g_wt1);
    cudaGetSymbolAddress((void**)&wt2, g_wt2);
    cudaGetSymbolAddress((void**)&wts, g_wts);
    cudaGetSymbolAddress((void**)&t1, g_t1);
    cudaGetSymbolAddress((void**)&t2, g_t2);
    cudaGetSymbolAddress((void**)&t3, g_t3);

    // launch #0..#4: SN(w1) + pad, so conv1 is launch #5 (ncu -s 5 profiles it)
    sn_zero<<<1, 256>>>();                                          // 0
    sn_tk_w<<<dim3(9, 8), 256>>>(w1, u1, t1, 256, 2304);            // 1
    sn_sk_w<<<256, 256>>>(w1, t1, 2304, 0);                         // 2
    prep_w<<<(256 * 256 * 9 + 255) / 256, 256>>>(w1, wt1, 256, 256, 9, 0, 1.f); // 3
    {
        const int t = 16 * 256 * 66 * 66;
        pad_x<<<(t + 255) / 256, 256>>>(x, xpad);                   // 4
    }
    // ---- conv1: xpad -> bufA fp16 [16,256,64,64], bias+lrelu ----
    conv_hmma<9, 1, 0><<<dim3(512, 2), 256, CONV_SMEM>>>(           // 5
        xpad, wt1, b1, bufA, 256, 66, 66, 256, 64, 64, 72);

    // ---- blur paths ----
    {
        const int t = 16 * 256 * 63 * 63;
        blur_h<float><<<(t + 255) / 256, 256>>>(x, bufB, 16 * 256, 64, 1, 63);
    }
    {
        const int t = 16 * 256 * 65 * 65;
        blur_h<__half><<<(t + 255) / 256, 256>>>(bufA, bufC, 16 * 256, 64, 2, 65);
    }

    // ---- SN(w2) + conv2 ----
    sn_tk_w<<<dim3(9, 8), 256>>>(w2, u2, t2, 512, 2304);
    sn_sk_w<<<512, 256>>>(w2, t2, 2304, 1);
    prep_w<<<(512 * 256 * 9 + 255) / 256, 256>>>(w2, wt2, 512, 256, 9, 1, 1.f);
    conv_hmma<9, 2, 1><<<dim3(128, 4), 256, CONV_SMEM>>>(
        bufC, wt2, b2, out, 256, 65, 65, 512, 32, 32, 72);

    // ---- SN(ws) + skip ----
    sn_tk_w<<<dim3(1, 8), 256>>>(wsk, us, t3, 512, 256);
    sn_sk_w<<<512, 256>>>(wsk, t3, 256, 2);
    prep_w<<<(512 * 256 + 255) / 256, 256>>>(wsk, wts, 512, 256, 1, 2, RSQRT2);
    conv_hmma<1, 2, 2><<<dim3(128, 4), 256, CONV_SMEM>>>(
        bufB, wts, nullptr, out, 256, 63, 63, 512, 32, 32, 8);
}

// round 6
// speedup vs baseline: 6.6203x; 1.2071x over previous
#include <cuda_runtime.h>
#include <cuda_fp16.h>
#include <math.h>
#include <stdint.h>

#define RSQRT2 0.70710678118654752f

// ---------------- device scratch (allocation-free rule) ----------------
__device__ float g_t1[2304];
__device__ float g_t2[2304];
__device__ float g_t3[256];
__device__ float g_nt2[3];
__device__ float g_ns2[3];
__device__ __half g_xpad[16 * 66 * 66 * 256];   // NHWC padded fp16 x
__device__ __half g_bufA[16 * 64 * 64 * 256];   // conv1 output NHWC
__device__ __half g_bufB[16 * 63 * 63 * 256];   // blur(x,pad1) NHWC
__device__ __half g_bufC[16 * 65 * 65 * 256];   // blur(conv1,pad2) NHWC
__device__ __half g_wt1[256 * 9 * 256];         // [oc][khw][ic] * 1/sigma
__device__ __half g_wt2[512 * 9 * 256];
__device__ __half g_wts[512 * 256];             // * 1/sigma * rsqrt2

// ---------------- helpers ----------------
__device__ __forceinline__ float warp_sum(float v) {
#pragma unroll
    for (int o = 16; o; o >>= 1) v += __shfl_down_sync(0xffffffffu, v, o);
    return v;
}

__device__ float block_sum(float v) {
    __shared__ float red[32];
    int lane = threadIdx.x & 31, w = threadIdx.x >> 5;
    v = warp_sum(v);
    if (lane == 0) red[w] = v;
    __syncthreads();
    float r = 0.f;
    if (w == 0) {
        int nw = (blockDim.x + 31) >> 5;
        r = (lane < nw) ? red[lane] : 0.f;
        r = warp_sum(r);
    }
    __syncthreads();
    return r;
}

__device__ __forceinline__ uint32_t smem_u32(const void* p) {
    uint32_t a;
    asm("{ .reg .u64 t; cvta.to.shared.u64 t, %1; cvt.u32.u64 %0, t; }" : "=r"(a) : "l"(p));
    return a;
}

__device__ __forceinline__ void sts32f(uint32_t a, float v) {
    asm volatile("st.shared.b32 [%0], %1;" :: "r"(a), "f"(v) : "memory");
}
__device__ __forceinline__ void sts128(uint32_t a, int4 v) {
    asm volatile("st.shared.v4.b32 [%0], {%1,%2,%3,%4};"
                 :: "r"(a), "r"(v.x), "r"(v.y), "r"(v.z), "r"(v.w) : "memory");
}
__device__ __forceinline__ float4 lds128f(uint32_t a) {
    float4 v;
    asm volatile("ld.shared.v4.f32 {%0,%1,%2,%3}, [%4];"
                 : "=f"(v.x), "=f"(v.y), "=f"(v.z), "=f"(v.w) : "r"(a));
    return v;
}

__device__ __forceinline__ void ldsm4(uint32_t* r, uint32_t addr) {
    asm volatile("ldmatrix.sync.aligned.m8n8.x4.shared.b16 {%0,%1,%2,%3}, [%4];"
                 : "=r"(r[0]), "=r"(r[1]), "=r"(r[2]), "=r"(r[3]) : "r"(addr));
}

__device__ __forceinline__ void mma16816(float* c, const uint32_t* a, const uint32_t* b) {
    asm volatile(
        "mma.sync.aligned.m16n8k16.row.col.f32.f16.f16.f32 "
        "{%0,%1,%2,%3}, {%4,%5,%6,%7}, {%8,%9}, {%0,%1,%2,%3};"
        : "+f"(c[0]), "+f"(c[1]), "+f"(c[2]), "+f"(c[3])
        : "r"(a[0]), "r"(a[1]), "r"(a[2]), "r"(a[3]), "r"(b[0]), "r"(b[1]));
}

// ---------------- spectral norm (wide) ----------------
__global__ void sn_zero() {
    int t = threadIdx.x;
    for (int i = t; i < 2304; i += 256) { g_t1[i] = 0.f; g_t2[i] = 0.f; }
    if (t < 256) g_t3[t] = 0.f;
    if (t < 3) { g_nt2[t] = 0.f; g_ns2[t] = 0.f; }
}

__global__ void sn_tk_w(const float* __restrict__ W, const float* __restrict__ u,
                        float* __restrict__ t, int H, int K) {
    int j = blockIdx.x * 256 + threadIdx.x;
    if (j >= K) return;
    int chunk = (H + 7) / 8;
    int i0 = blockIdx.y * chunk;
    int i1 = min(i0 + chunk, H);
    float s = 0.f;
    for (int i = i0; i < i1; i++)
        s = fmaf(W[(size_t)i * K + j], __ldg(u + i), s);
    atomicAdd(t + j, s);
}

__global__ void sn_sk_w(const float* __restrict__ W, const float* __restrict__ t,
                        int K, int idx) {
    int i = blockIdx.x;
    float s = 0.f;
    for (int j = threadIdx.x; j < K; j += blockDim.x)
        s = fmaf(W[(size_t)i * K + j], __ldg(t + j), s);
    s = block_sum(s);
    if (threadIdx.x == 0) atomicAdd(&g_ns2[idx], s * s);
    if (i == 0) {
        float a = 0.f;
        for (int j = threadIdx.x; j < K; j += blockDim.x) {
            float tv = __ldg(t + j);
            a = fmaf(tv, tv, a);
        }
        a = block_sum(a);
        if (threadIdx.x == 0) atomicAdd(&g_nt2[idx], a);
    }
}

__global__ void prep_w(const float* __restrict__ w, __half* __restrict__ wt,
                       int OC, int IC, int KHW, int sigIdx, float extra) {
    int idx = blockIdx.x * blockDim.x + threadIdx.x;
    int total = OC * IC * KHW;
    if (idx >= total) return;
    float nt = sqrtf(g_nt2[sigIdx]);
    float nwt = sqrtf(g_ns2[sigIdx]);
    float nwv = nwt / (nt + 1e-12f);
    float sigma = nwv * nwv / (nwv + 1e-12f);
    int khw = idx % KHW;
    int t = idx / KHW;
    int ic = t % IC;
    int oc = t / IC;
    float v = w[idx] * (extra / sigma);
    wt[((size_t)oc * KHW + khw) * IC + ic] = __float2half_rn(v);
}

// ---------------- input prep ----------------
__global__ void zero_half8(__half* p, int n8) {
    int i = blockIdx.x * blockDim.x + threadIdx.x;
    if (i < n8) reinterpret_cast<int4*>(p)[i] = make_int4(0, 0, 0, 0);
}

// x f32 NCHW [16,256,64,64] -> xpad fp16 NHWC [16,66,66,256] (interior at +1,+1)
__global__ void pad_x_t(const float* __restrict__ x, __half* __restrict__ xp) {
    __shared__ float sm[64][33];
    const int wt = blockIdx.x;    // 0..1  (w tiles of 32)
    const int ict = blockIdx.y;   // 0..3  (ic tiles of 64)
    const int plane = blockIdx.z; // img*64 + h
    const int img = plane >> 6, h = plane & 63;
    const int w0 = wt * 32, ic0 = ict * 64;
    const int tid = threadIdx.x;
    const int icl = tid >> 5, wl = tid & 31;
    const float* xb = x + (((size_t)img * 256 + ic0) * 64 + h) * 64 + w0;
#pragma unroll
    for (int r = 0; r < 8; r++)
        sm[icl + r * 8][wl] = xb[(size_t)(icl + r * 8) * 4096 + wl];
    __syncthreads();
    const int wIdx = tid >> 3, icq = tid & 7;
    __half hv[8];
#pragma unroll
    for (int k = 0; k < 8; k++) hv[k] = __float2half_rn(sm[icq * 8 + k][wIdx]);
    *reinterpret_cast<int4*>(
        xp + (((size_t)img * 66 + h + 1) * 66 + (w0 + wIdx + 1)) * 256 + ic0 + icq * 8) =
        *reinterpret_cast<int4*>(hv);
}

// ---------------- 4x4 binomial blur, NHWC, 8ch/thread ----------------
template <bool CHECK, int OFF>
__global__ void blur_nhwc(const __half* __restrict__ in, __half* __restrict__ out,
                          int inW, int outW) {
    int idx = blockIdx.x * blockDim.x + threadIdx.x;
    int total = 16 * outW * outW * 32;
    if (idx >= total) return;
    const int icq = idx & 31;
    int t = idx >> 5;
    const int x = t % outW; t /= outW;
    const int y = t % outW;
    const int img = t / outW;
    const __half* ib = in + (size_t)img * inW * inW * 256 + icq * 8;
    float acc[8];
#pragma unroll
    for (int q = 0; q < 8; q++) acc[q] = 0.f;
    const float kv[4] = {1.f, 3.f, 3.f, 1.f};
#pragma unroll
    for (int i = 0; i < 4; i++) {
        int yy = y + i + OFF;
        if (CHECK && ((unsigned)yy >= (unsigned)inW)) continue;
#pragma unroll
        for (int j = 0; j < 4; j++) {
            int xx = x + j + OFF;
            if (CHECK && ((unsigned)xx >= (unsigned)inW)) continue;
            int4 v = *reinterpret_cast<const int4*>(ib + ((size_t)yy * inW + xx) * 256);
            const __half* h = reinterpret_cast<const __half*>(&v);
            float w = kv[i] * kv[j];
#pragma unroll
            for (int q = 0; q < 8; q++) acc[q] = fmaf(w, __half2float(h[q]), acc[q]);
        }
    }
    __half res[8];
#pragma unroll
    for (int q = 0; q < 8; q++) res[q] = __float2half_rn(acc[q] * (1.f / 64.f));
    *reinterpret_cast<int4*>(
        out + ((size_t)img * outW * outW + (size_t)y * outW + x) * 256 + icq * 8) =
        *reinterpret_cast<int4*>(res);
}

// ---------------------------------------------------------------------------
// fp16 mma.sync implicit-GEMM conv, NHWC input. Block tile M=128 x N=128,
// K staged by 32 (one khw slice, 32 channels). A smem [m128][k32] pitch 80B,
// B smem [n128][k32] pitch 80B, both via non-trans ldmatrix.x4.
// EPI: 0 = bias+lrelu -> NHWC fp16 (direct), 1 = bias+lrelu -> NCHW f32,
//      2 = out*rsqrt2 + acc -> NCHW f32.
// ---------------------------------------------------------------------------
#define CONV_SMEM 40960

template <int KHW, int STRIDE, int EPI>
__global__ void __launch_bounds__(256, 2) conv_hmma(
    const __half* __restrict__ in, const __half* __restrict__ wt,
    const float* __restrict__ bias, void* __restrict__ outv,
    int INROW, int INIMG, int OC, int OH, int OW, int NS) {
    extern __shared__ char smem[];
    const uint32_t sb = smem_u32(smem);
    const uint32_t aOff0 = 0, aOff1 = 10240, bOff0 = 20480, bOff1 = 30720;

    const int tid = threadIdx.x;
    const int lane = tid & 31;
    const int wid = tid >> 5;
    const int wm = wid & 3;
    const int wn = wid >> 2;

    const int m0 = blockIdx.x * 128;
    const int ocb = blockIdx.y * 128;
    const int ohw = OH * OW;
    const int img = m0 / ohw;
    const int rbase = m0 - img * ohw;

    // per-thread gather mapping: 16 halves (one pixel / one oc, k-half kq)
    const int mIdx = tid >> 1;
    const int kq = tid & 1;
    const int m = rbase + mIdx;
    const int oh = m / OW;
    const int ow = m - oh * OW;
    const __half* abase = in + (size_t)img * INIMG + (size_t)(oh * STRIDE) * INROW +
                          (size_t)(ow * STRIDE) * 256 + kq * 16;
    const __half* bbase = wt + (size_t)(ocb + mIdx) * KHW * 256 + kq * 16;

    // ldmatrix addressing (non-trans): matrices = {rows+0 k0, rows+0 k8, rows+8 k0, rows+8 k8}
    const int lg = lane >> 3, lr = lane & 7;
    const uint32_t rowsel = (uint32_t)(lr + ((lg >> 1) << 3));
    const uint32_t kcol = (uint32_t)((lg & 1) << 4);
    const uint32_t aLM = sb + (wm * 32 + rowsel) * 80 + kcol;
    const uint32_t bLM = sb + (wn * 64 + rowsel) * 80 + kcol;

    float c[2][8][4];
#pragma unroll
    for (int mb = 0; mb < 2; mb++)
#pragma unroll
        for (int nb = 0; nb < 8; nb++)
#pragma unroll
            for (int q = 0; q < 4; q++) c[mb][nb][q] = 0.f;

    int4 ra[2], rb[2];

    auto LDG = [&](int s) {
        const int kk = s * 32;
        const int khw = (KHW == 1) ? 0 : (kk >> 8);
        const int ic0 = kk - (khw << 8);
        int kh = 0, kw = 0;
        if (KHW == 9) { kh = khw / 3; kw = khw - kh * 3; }
        const __half* ap = abase + (size_t)kh * INROW + kw * 256 + ic0;
        ra[0] = *reinterpret_cast<const int4*>(ap);
        ra[1] = *reinterpret_cast<const int4*>(ap + 8);
        const __half* bp = bbase + khw * 256 + ic0;
        rb[0] = *reinterpret_cast<const int4*>(bp);
        rb[1] = *reinterpret_cast<const int4*>(bp + 8);
    };

    auto STS = [&](uint32_t aB, uint32_t bB) {
        const uint32_t ao = aB + (uint32_t)(mIdx * 80 + kq * 32);
        sts128(ao, ra[0]);
        sts128(ao + 16, ra[1]);
        const uint32_t bo = bB + (uint32_t)(mIdx * 80 + kq * 32);
        sts128(bo, rb[0]);
        sts128(bo + 16, rb[1]);
    };

    auto MMA = [&](uint32_t aOff, uint32_t bOff) {
#pragma unroll
        for (int k16 = 0; k16 < 2; k16++) {
            uint32_t a[2][4], b[8][2];
#pragma unroll
            for (int mb = 0; mb < 2; mb++) {
                uint32_t r[4];
                ldsm4(r, aLM + aOff + k16 * 32 + mb * 1280);
                a[mb][0] = r[0]; a[mb][1] = r[2]; a[mb][2] = r[1]; a[mb][3] = r[3];
            }
#pragma unroll
            for (int nbp = 0; nbp < 4; nbp++) {
                uint32_t r[4];
                ldsm4(r, bLM + bOff + k16 * 32 + nbp * 1280);
                b[nbp * 2][0] = r[0]; b[nbp * 2][1] = r[1];
                b[nbp * 2 + 1][0] = r[2]; b[nbp * 2 + 1][1] = r[3];
            }
#pragma unroll
            for (int mb = 0; mb < 2; mb++)
#pragma unroll
                for (int nb = 0; nb < 8; nb++)
                    mma16816(c[mb][nb], a[mb], b[nb]);
        }
    };

    LDG(0);
    STS(aOff0 + sb - sb + (sb + aOff0) - (sb + aOff0) + (sb + aOff0), sb + bOff0); // placeholder avoided below
    // NOTE: call with explicit buffers:
    // (the line above is rewritten correctly here)
    // -- real pipeline --
    // (re-issue correctly)
    ;
    // correct prologue
    STS(sb + aOff0, sb + bOff0);
    if (NS > 1) LDG(1);
    __syncthreads();

    for (int s = 0; s < NS; s++) {
        const int b = s & 1;
        MMA(b ? aOff1 : aOff0, b ? bOff1 : bOff0);
        if (s + 1 < NS) STS(b ? (sb + aOff0) : (sb + aOff1), b ? (sb + bOff0) : (sb + bOff1));
        __syncthreads();
        if (s + 2 < NS) LDG(s + 2);
    }

    const int erow = lane >> 2;
    const int ecolp = (lane & 3) * 2;

    if (EPI == 0) {
        // direct NHWC fp16 store: out[pixel][oc]
        __half* ob = (__half*)outv;
#pragma unroll
        for (int mb = 0; mb < 2; mb++) {
            const size_t mrow = (size_t)(m0 + wm * 32 + mb * 16 + erow);
#pragma unroll
            for (int nb = 0; nb < 8; nb++) {
                const int col = ocb + wn * 64 + nb * 8 + ecolp;
                const float bv0 = __ldg(bias + col);
                const float bv1 = __ldg(bias + col + 1);
                const float* cc = c[mb][nb];
                float v0 = cc[0] + bv0, v1 = cc[1] + bv1;
                float v2 = cc[2] + bv0, v3 = cc[3] + bv1;
                v0 = v0 > 0.f ? v0 : 0.2f * v0;
                v1 = v1 > 0.f ? v1 : 0.2f * v1;
                v2 = v2 > 0.f ? v2 : 0.2f * v2;
                v3 = v3 > 0.f ? v3 : 0.2f * v3;
                __half2 h0 = __floats2half2_rn(v0, v1);
                __half2 h1 = __floats2half2_rn(v2, v3);
                *reinterpret_cast<__half2*>(ob + mrow * 256 + col) = h0;
                *reinterpret_cast<__half2*>(ob + (mrow + 8) * 256 + col) = h1;
            }
        }
    } else {
        // smem transpose -> NCHW f32 coalesced
        for (int nc = 0; nc < 4; nc++) {
            if (wn == (nc >> 1)) {
                const int nbBase = (nc & 1) * 4;
#pragma unroll
                for (int mb = 0; mb < 2; mb++) {
                    const int mrow = wm * 32 + mb * 16 + erow;
#pragma unroll
                    for (int j = 0; j < 4; j++) {
                        const int nb = nbBase + j;
                        const int ocl = j * 8 + ecolp;
                        const float* cc = c[mb][nb];
                        sts32f(sb + (uint32_t)(ocl * 544 + mrow * 4), cc[0]);
                        sts32f(sb + (uint32_t)((ocl + 1) * 544 + mrow * 4), cc[1]);
                        sts32f(sb + (uint32_t)(ocl * 544 + (mrow + 8) * 4), cc[2]);
                        sts32f(sb + (uint32_t)((ocl + 1) * 544 + (mrow + 8) * 4), cc[3]);
                    }
                }
            }
            __syncthreads();
#pragma unroll
            for (int p = 0; p < 4; p++) {
                const int idx = p * 256 + tid;
                const int ocl = idx >> 5;
                const int mq = (idx & 31) * 4;
                float4 v = lds128f(sb + (uint32_t)(ocl * 544 + mq * 4));
                const int oc = ocb + nc * 32 + ocl;
                const size_t go = ((size_t)img * OC + oc) * ohw + rbase + mq;
                if (EPI == 1) {
                    const float bv = __ldg(bias + oc);
                    v.x += bv; v.y += bv; v.z += bv; v.w += bv;
                    v.x = v.x > 0.f ? v.x : 0.2f * v.x;
                    v.y = v.y > 0.f ? v.y : 0.2f * v.y;
                    v.z = v.z > 0.f ? v.z : 0.2f * v.z;
                    v.w = v.w > 0.f ? v.w : 0.2f * v.w;
                    *reinterpret_cast<float4*>((float*)outv + go) = v;
                } else {
                    float* op = (float*)outv + go;
                    float4 o = *reinterpret_cast<const float4*>(op);
                    o.x = o.x * RSQRT2 + v.x;
                    o.y = o.y * RSQRT2 + v.y;
                    o.z = o.z * RSQRT2 + v.z;
                    o.w = o.w * RSQRT2 + v.w;
                    *reinterpret_cast<float4*>(op) = o;
                }
            }
            __syncthreads();
        }
    }
}

// ---------------------------------------------------------------------------
extern "C" void kernel_launch(void* const* d_in, const int* in_sizes, int n_in,
                              void* d_out, int out_size) {
    const float* x   = (const float*)d_in[0];
    const float* w1  = (const float*)d_in[1];
    const float* u1  = (const float*)d_in[2];
    const float* b1  = (const float*)d_in[4];
    const float* w2  = (const float*)d_in[5];
    const float* u2  = (const float*)d_in[6];
    const float* b2  = (const float*)d_in[8];
    const float* wsk = (const float*)d_in[9];
    const float* us  = (const float*)d_in[10];
    float* out = (float*)d_out;

    __half *xpad, *bufA, *bufB, *bufC, *wt1, *wt2, *wts;
    float *t1, *t2, *t3;
    cudaGetSymbolAddress((void**)&xpad, g_xpad);
    cudaGetSymbolAddress((void**)&bufA, g_bufA);
    cudaGetSymbolAddress((void**)&bufB, g_bufB);
    cudaGetSymbolAddress((void**)&bufC, g_bufC);
    cudaGetSymbolAddress((void**)&wt1, g_wt1);
    cudaGetSymbolAddress((void**)&wt2, g_wt2);
    cudaGetSymbolAddress((void**)&wts, g_wts);
    cudaGetSymbolAddress((void**)&t1, g_t1);
    cudaGetSymbolAddress((void**)&t2, g_t2);
    cudaGetSymbolAddress((void**)&t3, g_t3);

    // ---- SN(w1) + weight prep ----
    sn_zero<<<1, 256>>>();
    sn_tk_w<<<dim3(9, 8), 256>>>(w1, u1, t1, 256, 2304);
    sn_sk_w<<<256, 256>>>(w1, t1, 2304, 0);
    prep_w<<<(256 * 256 * 9 + 255) / 256, 256>>>(w1, wt1, 256, 256, 9, 0, 1.f);

    // ---- input prep: zero halo + NCHW->NHWC transpose ----
    {
        const int n8 = 16 * 66 * 66 * 256 / 8;
        zero_half8<<<(n8 + 255) / 256, 256>>>(xpad, n8);
        pad_x_t<<<dim3(2, 4, 16 * 64), 256>>>(x, xpad);
    }

    // ---- conv1: xpad -> bufA NHWC [16,64,64,256], bias+lrelu ----
    conv_hmma<9, 1, 0><<<dim3(512, 2), 256, CONV_SMEM>>>(
        xpad, wt1, b1, bufA, 66 * 256, 66 * 66 * 256, 256, 64, 64, 72);

    // ---- blurs ----
    {
        const int t = 16 * 63 * 63 * 32;
        blur_nhwc<false, 0><<<(t + 255) / 256, 256>>>(xpad, bufB, 66, 63);
    }
    {
        const int t = 16 * 65 * 65 * 32;
        blur_nhwc<true, -2><<<(t + 255) / 256, 256>>>(bufA, bufC, 64, 65);
    }

    // ---- SN(w2) + conv2 -> d_out NCHW f32 ----
    sn_tk_w<<<dim3(9, 8), 256>>>(w2, u2, t2, 512, 2304);
    sn_sk_w<<<512, 256>>>(w2, t2, 2304, 1);
    prep_w<<<(512 * 256 * 9 + 255) / 256, 256>>>(w2, wt2, 512, 256, 9, 1, 1.f);
    conv_hmma<9, 2, 1><<<dim3(128, 4), 256, CONV_SMEM>>>(
        bufC, wt2, b2, out, 65 * 256, 65 * 65 * 256, 512, 32, 32, 72);

    // ---- SN(ws) + skip 1x1 s2: out = out*rsqrt2 + acc ----
    sn_tk_w<<<dim3(1, 8), 256>>>(wsk, us, t3, 512, 256);
    sn_sk_w<<<512, 256>>>(wsk, t3, 256, 2);
    prep_w<<<(512 * 256 + 255) / 256, 256>>>(wsk, wts, 512, 256, 1, 2, RSQRT2);
    conv_hmma<1, 2, 2><<<dim3(128, 4), 256, CONV_SMEM>>>(
        bufB, wts, nullptr, out, 63 * 256, 63 * 63 * 256, 512, 32, 32, 8);
}

// round 8
// speedup vs baseline: 7.0555x; 1.0657x over previous
#include <cuda_runtime.h>
#include <cuda_fp16.h>
#include <math.h>
#include <stdint.h>

#define RSQRT2 0.70710678118654752f

// ---------------- device scratch (allocation-free rule) ----------------
__device__ float g_t1[2304];
__device__ float g_t2[2304];
__device__ float g_t3[256];
__device__ float g_nt2[3];
__device__ float g_ns2[3];
__device__ __half g_xpad[16 * 66 * 66 * 256];   // NHWC padded fp16 x
__device__ __half g_bufA[16 * 64 * 64 * 256];   // conv1 output NHWC
__device__ __half g_bufB[16 * 63 * 63 * 256];   // blur(x,pad1) NHWC
__device__ __half g_bufC[16 * 65 * 65 * 256];   // blur(conv1,pad2) NHWC
__device__ __half g_wt1[256 * 9 * 256];         // [oc][khw][ic] * 1/sigma
__device__ __half g_wt2[512 * 9 * 256];
__device__ __half g_wts[512 * 256];             // * 1/sigma * rsqrt2

// ---------------- helpers ----------------
__device__ __forceinline__ float warp_sum(float v) {
#pragma unroll
    for (int o = 16; o; o >>= 1) v += __shfl_down_sync(0xffffffffu, v, o);
    return v;
}

__device__ float block_sum(float v) {
    __shared__ float red[32];
    int lane = threadIdx.x & 31, w = threadIdx.x >> 5;
    v = warp_sum(v);
    if (lane == 0) red[w] = v;
    __syncthreads();
    float r = 0.f;
    if (w == 0) {
        int nw = (blockDim.x + 31) >> 5;
        r = (lane < nw) ? red[lane] : 0.f;
        r = warp_sum(r);
    }
    __syncthreads();
    return r;
}

__device__ __forceinline__ uint32_t smem_u32(const void* p) {
    uint32_t a;
    asm("{ .reg .u64 t; cvta.to.shared.u64 t, %1; cvt.u32.u64 %0, t; }" : "=r"(a) : "l"(p));
    return a;
}

__device__ __forceinline__ void sts32f(uint32_t a, float v) {
    asm volatile("st.shared.b32 [%0], %1;" :: "r"(a), "f"(v) : "memory");
}
__device__ __forceinline__ float4 lds128f(uint32_t a) {
    float4 v;
    asm volatile("ld.shared.v4.f32 {%0,%1,%2,%3}, [%4];"
                 : "=f"(v.x), "=f"(v.y), "=f"(v.z), "=f"(v.w) : "r"(a));
    return v;
}

__device__ __forceinline__ void cpa16(uint32_t s, const void* g) {
    asm volatile("cp.async.cg.shared.global [%0], [%1], 16;" :: "r"(s), "l"(g) : "memory");
}
__device__ __forceinline__ void cp_commit() {
    asm volatile("cp.async.commit_group;" ::: "memory");
}
template <int N>
__device__ __forceinline__ void cp_wait() {
    asm volatile("cp.async.wait_group %0;" :: "n"(N) : "memory");
}

__device__ __forceinline__ void ldsm4(uint32_t* r, uint32_t addr) {
    asm volatile("ldmatrix.sync.aligned.m8n8.x4.shared.b16 {%0,%1,%2,%3}, [%4];"
                 : "=r"(r[0]), "=r"(r[1]), "=r"(r[2]), "=r"(r[3]) : "r"(addr));
}

__device__ __forceinline__ void mma16816(float* c, const uint32_t* a, const uint32_t* b) {
    asm volatile(
        "mma.sync.aligned.m16n8k16.row.col.f32.f16.f16.f32 "
        "{%0,%1,%2,%3}, {%4,%5,%6,%7}, {%8,%9}, {%0,%1,%2,%3};"
        : "+f"(c[0]), "+f"(c[1]), "+f"(c[2]), "+f"(c[3])
        : "r"(a[0]), "r"(a[1]), "r"(a[2]), "r"(a[3]), "r"(b[0]), "r"(b[1]));
}

// ---------------- spectral norm (wide) ----------------
__global__ void sn_zero() {
    int t = threadIdx.x;
    for (int i = t; i < 2304; i += 256) { g_t1[i] = 0.f; g_t2[i] = 0.f; }
    if (t < 256) g_t3[t] = 0.f;
    if (t < 3) { g_nt2[t] = 0.f; g_ns2[t] = 0.f; }
}

__global__ void sn_tk_w(const float* __restrict__ W, const float* __restrict__ u,
                        float* __restrict__ t, int H, int K) {
    int j = blockIdx.x * 256 + threadIdx.x;
    if (j >= K) return;
    int chunk = (H + 7) / 8;
    int i0 = blockIdx.y * chunk;
    int i1 = min(i0 + chunk, H);
    float s = 0.f;
    for (int i = i0; i < i1; i++)
        s = fmaf(W[(size_t)i * K + j], __ldg(u + i), s);
    atomicAdd(t + j, s);
}

__global__ void sn_sk_w(const float* __restrict__ W, const float* __restrict__ t,
                        int K, int idx) {
    int i = blockIdx.x;
    float s = 0.f;
    for (int j = threadIdx.x; j < K; j += blockDim.x)
        s = fmaf(W[(size_t)i * K + j], __ldg(t + j), s);
    s = block_sum(s);
    if (threadIdx.x == 0) atomicAdd(&g_ns2[idx], s * s);
    if (i == 0) {
        float a = 0.f;
        for (int j = threadIdx.x; j < K; j += blockDim.x) {
            float tv = __ldg(t + j);
            a = fmaf(tv, tv, a);
        }
        a = block_sum(a);
        if (threadIdx.x == 0) atomicAdd(&g_nt2[idx], a);
    }
}

__global__ void prep_w(const float* __restrict__ w, __half* __restrict__ wt,
                       int OC, int IC, int KHW, int sigIdx, float extra) {
    int idx = blockIdx.x * blockDim.x + threadIdx.x;
    int total = OC * IC * KHW;
    if (idx >= total) return;
    float nt = sqrtf(g_nt2[sigIdx]);
    float nwt = sqrtf(g_ns2[sigIdx]);
    float nwv = nwt / (nt + 1e-12f);
    float sigma = nwv * nwv / (nwv + 1e-12f);
    int khw = idx % KHW;
    int t = idx / KHW;
    int ic = t % IC;
    int oc = t / IC;
    float v = w[idx] * (extra / sigma);
    wt[((size_t)oc * KHW + khw) * IC + ic] = __float2half_rn(v);
}

// ---------------- input prep ----------------
// zero only the 1-pixel halo of xpad (260 edge pixels per image)
__global__ void zero_halo(__half* xp) {
    int i = blockIdx.x * blockDim.x + threadIdx.x;
    const int per = 260 * 32;  // int4 stores per image
    if (i >= 16 * per) return;
    int img = i / per;
    int r = i - img * per;
    int pix = r >> 5, q = r & 31;
    int h, w;
    if (pix < 66) { h = 0; w = pix; }
    else if (pix < 132) { h = 65; w = pix - 66; }
    else if (pix < 196) { h = pix - 131; w = 0; }
    else { h = pix - 195; w = 65; }
    reinterpret_cast<int4*>(xp + (((size_t)img * 66 + h) * 66 + w) * 256)[q] =
        make_int4(0, 0, 0, 0);
}

// x f32 NCHW [16,256,64,64] -> xpad fp16 NHWC [16,66,66,256] (interior at +1,+1)
__global__ void pad_x_t(const float* __restrict__ x, __half* __restrict__ xp) {
    __shared__ float sm[64][33];
    const int wt = blockIdx.x;
    const int ict = blockIdx.y;
    const int plane = blockIdx.z;
    const int img = plane >> 6, h = plane & 63;
    const int w0 = wt * 32, ic0 = ict * 64;
    const int tid = threadIdx.x;
    const int icl = tid >> 5, wl = tid & 31;
    const float* xb = x + (((size_t)img * 256 + ic0) * 64 + h) * 64 + w0;
#pragma unroll
    for (int r = 0; r < 8; r++)
        sm[icl + r * 8][wl] = xb[(size_t)(icl + r * 8) * 4096 + wl];
    __syncthreads();
    const int wIdx = tid >> 3, icq = tid & 7;
    __half hv[8];
#pragma unroll
    for (int k = 0; k < 8; k++) hv[k] = __float2half_rn(sm[icq * 8 + k][wIdx]);
    *reinterpret_cast<int4*>(
        xp + (((size_t)img * 66 + h + 1) * 66 + (w0 + wIdx + 1)) * 256 + ic0 + icq * 8) =
        *reinterpret_cast<int4*>(hv);
}

// ---------------- 4x4 binomial blur, NHWC, 8ch/thread ----------------
template <bool CHECK, int OFF>
__global__ void blur_nhwc(const __half* __restrict__ in, __half* __restrict__ out,
                          int inW, int outW) {
    int idx = blockIdx.x * blockDim.x + threadIdx.x;
    int total = 16 * outW * outW * 32;
    if (idx >= total) return;
    const int icq = idx & 31;
    int t = idx >> 5;
    const int x = t % outW; t /= outW;
    const int y = t % outW;
    const int img = t / outW;
    const __half* ib = in + (size_t)img * inW * inW * 256 + icq * 8;
    float acc[8];
#pragma unroll
    for (int q = 0; q < 8; q++) acc[q] = 0.f;
    const float kv[4] = {1.f, 3.f, 3.f, 1.f};
#pragma unroll
    for (int i = 0; i < 4; i++) {
        int yy = y + i + OFF;
        if (CHECK && ((unsigned)yy >= (unsigned)inW)) continue;
#pragma unroll
        for (int j = 0; j < 4; j++) {
            int xx = x + j + OFF;
            if (CHECK && ((unsigned)xx >= (unsigned)inW)) continue;
            int4 v = *reinterpret_cast<const int4*>(ib + ((size_t)yy * inW + xx) * 256);
            const __half* h = reinterpret_cast<const __half*>(&v);
            float w = kv[i] * kv[j];
#pragma unroll
            for (int q = 0; q < 8; q++) acc[q] = fmaf(w, __half2float(h[q]), acc[q]);
        }
    }
    __half res[8];
#pragma unroll
    for (int q = 0; q < 8; q++) res[q] = __float2half_rn(acc[q] * (1.f / 64.f));
    *reinterpret_cast<int4*>(
        out + ((size_t)img * outW * outW + (size_t)y * outW + x) * 256 + icq * 8) =
        *reinterpret_cast<int4*>(res);
}

// ---------------------------------------------------------------------------
// fp16 mma.sync implicit-GEMM conv, NHWC, cp.async 3-stage ring.
// Block tile M=128 x N=128, K staged by 32. Stage = A[128][k32]p80 + B same,
// 20480 B; 3 stages = 61440 B (needs MaxDynamicSharedMemorySize attr).
// EPI: 0 = bias+lrelu -> NHWC fp16, 1 = bias+lrelu -> NCHW f32,
//      2 = out*rsqrt2 + acc -> NCHW f32.
// ---------------------------------------------------------------------------
#define STAGE_BYTES 20480
#define CONV_SMEM (3 * STAGE_BYTES)

template <int KHW, int STRIDE, int EPI>
__global__ void __launch_bounds__(256, 2) conv_hmma(
    const __half* __restrict__ in, const __half* __restrict__ wt,
    const float* __restrict__ bias, void* __restrict__ outv,
    int INROW, int INIMG, int OC, int OH, int OW, int NS) {
    extern __shared__ char smem[];
    const uint32_t sb = smem_u32(smem);

    const int tid = threadIdx.x;
    const int lane = tid & 31;
    const int wid = tid >> 5;
    const int wm = wid & 3;
    const int wn = wid >> 2;

    const int m0 = blockIdx.x * 128;
    const int ocb = blockIdx.y * 128;
    const int ohw = OH * OW;
    const int img = m0 / ohw;
    const int rbase = m0 - img * ohw;

    const int mIdx = tid >> 1;
    const int kq = tid & 1;
    const int m = rbase + mIdx;
    const int oh = m / OW;
    const int ow = m - oh * OW;
    const __half* abase = in + (size_t)img * INIMG + (size_t)(oh * STRIDE) * INROW +
                          (size_t)(ow * STRIDE) * 256 + kq * 16;
    const __half* bbase = wt + (size_t)(ocb + mIdx) * KHW * 256 + kq * 16;
    const uint32_t stsOff = (uint32_t)(mIdx * 80 + kq * 32);

    const int lg = lane >> 3, lr = lane & 7;
    const uint32_t rowsel = (uint32_t)(lr + ((lg >> 1) << 3));
    const uint32_t kcol = (uint32_t)((lg & 1) << 4);
    const uint32_t aLMr = (wm * 32 + rowsel) * 80 + kcol;
    const uint32_t bLMr = (wn * 64 + rowsel) * 80 + kcol;

    float c[2][8][4];
#pragma unroll
    for (int mb = 0; mb < 2; mb++)
#pragma unroll
        for (int nb = 0; nb < 8; nb++)
#pragma unroll
            for (int q = 0; q < 4; q++) c[mb][nb][q] = 0.f;

    auto CPA = [&](int s, uint32_t base) {
        const int kk = s * 32;
        const int khw = (KHW == 1) ? 0 : (kk >> 8);
        const int ic0 = kk - (khw << 8);
        int kh = 0, kw = 0;
        if (KHW == 9) { kh = khw / 3; kw = khw - kh * 3; }
        const __half* ap = abase + (size_t)kh * INROW + kw * 256 + ic0;
        cpa16(base + stsOff, ap);
        cpa16(base + stsOff + 16, ap + 8);
        const __half* bp = bbase + khw * 256 + ic0;
        cpa16(base + 10240 + stsOff, bp);
        cpa16(base + 10240 + stsOff + 16, bp + 8);
        cp_commit();
    };

    auto MMA = [&](uint32_t base) {
        const uint32_t aLM = base + aLMr;
        const uint32_t bLM = base + 10240 + bLMr;
#pragma unroll
        for (int k16 = 0; k16 < 2; k16++) {
            uint32_t a[2][4], b[8][2];
#pragma unroll
            for (int mb = 0; mb < 2; mb++) {
                uint32_t r[4];
                ldsm4(r, aLM + k16 * 32 + mb * 1280);
                a[mb][0] = r[0]; a[mb][1] = r[2]; a[mb][2] = r[1]; a[mb][3] = r[3];
            }
#pragma unroll
            for (int nbp = 0; nbp < 4; nbp++) {
                uint32_t r[4];
                ldsm4(r, bLM + k16 * 32 + nbp * 1280);
                b[nbp * 2][0] = r[0]; b[nbp * 2][1] = r[1];
                b[nbp * 2 + 1][0] = r[2]; b[nbp * 2 + 1][1] = r[3];
            }
#pragma unroll
            for (int mb = 0; mb < 2; mb++)
#pragma unroll
                for (int nb = 0; nb < 8; nb++)
                    mma16816(c[mb][nb], a[mb], b[nb]);
        }
    };

    CPA(0, sb);
    if (NS > 1) CPA(1, sb + STAGE_BYTES);
    int ring = 0;
    for (int s = 0; s < NS; s++) {
        if (s + 1 < NS) cp_wait<1>(); else cp_wait<0>();
        __syncthreads();
        const uint32_t cur = sb + ring * STAGE_BYTES;
        MMA(cur);
        if (s + 2 < NS) {
            int nxt = ring + 2; if (nxt >= 3) nxt -= 3;
            CPA(s + 2, sb + nxt * STAGE_BYTES);
        }
        ring = (ring == 2) ? 0 : ring + 1;
    }
    __syncthreads();

    const int erow = lane >> 2;
    const int ecolp = (lane & 3) * 2;

    if (EPI == 0) {
        __half* ob = (__half*)outv;
#pragma unroll
        for (int mb = 0; mb < 2; mb++) {
            const size_t mrow = (size_t)(m0 + wm * 32 + mb * 16 + erow);
#pragma unroll
            for (int nb = 0; nb < 8; nb++) {
                const int col = ocb + wn * 64 + nb * 8 + ecolp;
                const float bv0 = __ldg(bias + col);
                const float bv1 = __ldg(bias + col + 1);
                const float* cc = c[mb][nb];
                float v0 = cc[0] + bv0, v1 = cc[1] + bv1;
                float v2 = cc[2] + bv0, v3 = cc[3] + bv1;
                v0 = v0 > 0.f ? v0 : 0.2f * v0;
                v1 = v1 > 0.f ? v1 : 0.2f * v1;
                v2 = v2 > 0.f ? v2 : 0.2f * v2;
                v3 = v3 > 0.f ? v3 : 0.2f * v3;
                __half2 h0 = __floats2half2_rn(v0, v1);
                __half2 h1 = __floats2half2_rn(v2, v3);
                *reinterpret_cast<__half2*>(ob + mrow * 256 + col) = h0;
                *reinterpret_cast<__half2*>(ob + (mrow + 8) * 256 + col) = h1;
            }
        }
    } else {
        for (int nc = 0; nc < 4; nc++) {
            if (wn == (nc >> 1)) {
                const int nbBase = (nc & 1) * 4;
#pragma unroll
                for (int mb = 0; mb < 2; mb++) {
                    const int mrow = wm * 32 + mb * 16 + erow;
#pragma unroll
                    for (int j = 0; j < 4; j++) {
                        const int nb = nbBase + j;
                        const int ocl = j * 8 + ecolp;
                        const float* cc = c[mb][nb];
                        sts32f(sb + (uint32_t)(ocl * 544 + mrow * 4), cc[0]);
                        sts32f(sb + (uint32_t)((ocl + 1) * 544 + mrow * 4), cc[1]);
                        sts32f(sb + (uint32_t)(ocl * 544 + (mrow + 8) * 4), cc[2]);
                        sts32f(sb + (uint32_t)((ocl + 1) * 544 + (mrow + 8) * 4), cc[3]);
                    }
                }
            }
            __syncthreads();
#pragma unroll
            for (int p = 0; p < 4; p++) {
                const int idx = p * 256 + tid;
                const int ocl = idx >> 5;
                const int mq = (idx & 31) * 4;
                float4 v = lds128f(sb + (uint32_t)(ocl * 544 + mq * 4));
                const int oc = ocb + nc * 32 + ocl;
                const size_t go = ((size_t)img * OC + oc) * ohw + rbase + mq;
                if (EPI == 1) {
                    const float bv = __ldg(bias + oc);
                    v.x += bv; v.y += bv; v.z += bv; v.w += bv;
                    v.x = v.x > 0.f ? v.x : 0.2f * v.x;
                    v.y = v.y > 0.f ? v.y : 0.2f * v.y;
                    v.z = v.z > 0.f ? v.z : 0.2f * v.z;
                    v.w = v.w > 0.f ? v.w : 0.2f * v.w;
                    *reinterpret_cast<float4*>((float*)outv + go) = v;
                } else {
                    float* op = (float*)outv + go;
                    float4 o = *reinterpret_cast<const float4*>(op);
                    o.x = o.x * RSQRT2 + v.x;
                    o.y = o.y * RSQRT2 + v.y;
                    o.z = o.z * RSQRT2 + v.z;
                    o.w = o.w * RSQRT2 + v.w;
                    *reinterpret_cast<float4*>(op) = o;
                }
            }
            __syncthreads();
        }
    }
}

// ---------------------------------------------------------------------------
extern "C" void kernel_launch(void* const* d_in, const int* in_sizes, int n_in,
                              void* d_out, int out_size) {
    const float* x   = (const float*)d_in[0];
    const float* w1  = (const float*)d_in[1];
    const float* u1  = (const float*)d_in[2];
    const float* b1  = (const float*)d_in[4];
    const float* w2  = (const float*)d_in[5];
    const float* u2  = (const float*)d_in[6];
    const float* b2  = (const float*)d_in[8];
    const float* wsk = (const float*)d_in[9];
    const float* us  = (const float*)d_in[10];
    float* out = (float*)d_out;

    __half *xpad, *bufA, *bufB, *bufC, *wt1, *wt2, *wts;
    float *t1, *t2, *t3;
    cudaGetSymbolAddress((void**)&xpad, g_xpad);
    cudaGetSymbolAddress((void**)&bufA, g_bufA);
    cudaGetSymbolAddress((void**)&bufB, g_bufB);
    cudaGetSymbolAddress((void**)&bufC, g_bufC);
    cudaGetSymbolAddress((void**)&wt1, g_wt1);
    cudaGetSymbolAddress((void**)&wt2, g_wt2);
    cudaGetSymbolAddress((void**)&wts, g_wts);
    cudaGetSymbolAddress((void**)&t1, g_t1);
    cudaGetSymbolAddress((void**)&t2, g_t2);
    cudaGetSymbolAddress((void**)&t3, g_t3);

    // raise dynamic smem limit for the 3-stage ring (61440 B > 48 KB default)
    cudaFuncSetAttribute(conv_hmma<9, 1, 0>,
                         cudaFuncAttributeMaxDynamicSharedMemorySize, CONV_SMEM);
    cudaFuncSetAttribute(conv_hmma<9, 2, 1>,
                         cudaFuncAttributeMaxDynamicSharedMemorySize, CONV_SMEM);
    cudaFuncSetAttribute(conv_hmma<1, 2, 2>,
                         cudaFuncAttributeMaxDynamicSharedMemorySize, CONV_SMEM);

    // ---- SN(w1) + weight prep ----
    sn_zero<<<1, 256>>>();
    sn_tk_w<<<dim3(9, 8), 256>>>(w1, u1, t1, 256, 2304);
    sn_sk_w<<<256, 256>>>(w1, t1, 2304, 0);
    prep_w<<<(256 * 256 * 9 + 255) / 256, 256>>>(w1, wt1, 256, 256, 9, 0, 1.f);

    // ---- input prep: halo zero + NCHW->NHWC transpose ----
    {
        const int n = 16 * 260 * 32;
        zero_halo<<<(n + 255) / 256, 256>>>(xpad);
        pad_x_t<<<dim3(2, 4, 16 * 64), 256>>>(x, xpad);
    }

    // ---- conv1: xpad -> bufA NHWC [16,64,64,256], bias+lrelu ----
    conv_hmma<9, 1, 0><<<dim3(512, 2), 256, CONV_SMEM>>>(
        xpad, wt1, b1, bufA, 66 * 256, 66 * 66 * 256, 256, 64, 64, 72);

    // ---- blurs ----
    {
        const int t = 16 * 63 * 63 * 32;
        blur_nhwc<false, 0><<<(t + 255) / 256, 256>>>(xpad, bufB, 66, 63);
    }
    {
        const int t = 16 * 65 * 65 * 32;
        blur_nhwc<true, -2><<<(t + 255) / 256, 256>>>(bufA, bufC, 64, 65);
    }

    // ---- SN(w2) + conv2 -> d_out NCHW f32 ----
    sn_tk_w<<<dim3(9, 8), 256>>>(w2, u2, t2, 512, 2304);
    sn_sk_w<<<512, 256>>>(w2, t2, 2304, 1);
    prep_w<<<(512 * 256 * 9 + 255) / 256, 256>>>(w2, wt2, 512, 256, 9, 1, 1.f);
    conv_hmma<9, 2, 1><<<dim3(128, 4), 256, CONV_SMEM>>>(
        bufC, wt2, b2, out, 65 * 256, 65 * 65 * 256, 512, 32, 32, 72);

    // ---- SN(ws) + skip 1x1 s2: out = out*rsqrt2 + acc ----
    sn_tk_w<<<dim3(1, 8), 256>>>(wsk, us, t3, 512, 256);
    sn_sk_w<<<512, 256>>>(wsk, t3, 256, 2);
    prep_w<<<(512 * 256 + 255) / 256, 256>>>(wsk, wts, 512, 256, 1, 2, RSQRT2);
    conv_hmma<1, 2, 2><<<dim3(128, 4), 256, CONV_SMEM>>>(
        bufB, wts, nullptr, out, 63 * 256, 63 * 63 * 256, 512, 32, 32, 8);
}

// round 10
// speedup vs baseline: 7.1665x; 1.0157x over previous
#include <cuda_runtime.h>
#include <cuda_fp16.h>
#include <math.h>
#include <stdint.h>

#define RSQRT2 0.70710678118654752f

// ---------------- device scratch (allocation-free rule) ----------------
__device__ float g_t1[2304];
__device__ float g_t2[2304];
__device__ float g_t3[256];
__device__ float g_nt2[3];
__device__ float g_ns2[3];
__device__ __half g_xpad[16 * 66 * 66 * 256];   // NHWC padded fp16 x
__device__ __half g_bufA[16 * 64 * 64 * 256];   // conv1 output NHWC
__device__ __half g_bufB[16 * 63 * 63 * 256];   // blur(x,pad1) NHWC
__device__ __half g_bufC[16 * 65 * 65 * 256];   // blur(conv1,pad2) NHWC
__device__ __half g_wt1[256 * 9 * 256];         // [oc][khw][ic] * 1/sigma
__device__ __half g_wt2[512 * 9 * 256];
__device__ __half g_wts[512 * 256];             // * 1/sigma * rsqrt2

// ---------------- helpers ----------------
__device__ __forceinline__ float warp_sum(float v) {
#pragma unroll
    for (int o = 16; o; o >>= 1) v += __shfl_down_sync(0xffffffffu, v, o);
    return v;
}

__device__ float block_sum(float v) {
    __shared__ float red[32];
    int lane = threadIdx.x & 31, w = threadIdx.x >> 5;
    v = warp_sum(v);
    if (lane == 0) red[w] = v;
    __syncthreads();
    float r = 0.f;
    if (w == 0) {
        int nw = (blockDim.x + 31) >> 5;
        r = (lane < nw) ? red[lane] : 0.f;
        r = warp_sum(r);
    }
    __syncthreads();
    return r;
}

__device__ __forceinline__ uint32_t smem_u32(const void* p) {
    uint32_t a;
    asm("{ .reg .u64 t; cvta.to.shared.u64 t, %1; cvt.u32.u64 %0, t; }" : "=r"(a) : "l"(p));
    return a;
}

__device__ __forceinline__ void sts32f(uint32_t a, float v) {
    asm volatile("st.shared.b32 [%0], %1;" :: "r"(a), "f"(v) : "memory");
}
__device__ __forceinline__ float4 lds128f(uint32_t a) {
    float4 v;
    asm volatile("ld.shared.v4.f32 {%0,%1,%2,%3}, [%4];"
                 : "=f"(v.x), "=f"(v.y), "=f"(v.z), "=f"(v.w) : "r"(a));
    return v;
}

__device__ __forceinline__ void cpa16(uint32_t s, const void* g) {
    asm volatile("cp.async.cg.shared.global [%0], [%1], 16;" :: "r"(s), "l"(g) : "memory");
}
__device__ __forceinline__ void cp_commit() {
    asm volatile("cp.async.commit_group;" ::: "memory");
}
template <int N>
__device__ __forceinline__ void cp_wait() {
    asm volatile("cp.async.wait_group %0;" :: "n"(N) : "memory");
}

__device__ __forceinline__ void ldsm4(uint32_t* r, uint32_t addr) {
    asm volatile("ldmatrix.sync.aligned.m8n8.x4.shared.b16 {%0,%1,%2,%3}, [%4];"
                 : "=r"(r[0]), "=r"(r[1]), "=r"(r[2]), "=r"(r[3]) : "r"(addr));
}

__device__ __forceinline__ void mma16816(float* c, const uint32_t* a, const uint32_t* b) {
    asm volatile(
        "mma.sync.aligned.m16n8k16.row.col.f32.f16.f16.f32 "
        "{%0,%1,%2,%3}, {%4,%5,%6,%7}, {%8,%9}, {%0,%1,%2,%3};"
        : "+f"(c[0]), "+f"(c[1]), "+f"(c[2]), "+f"(c[3])
        : "r"(a[0]), "r"(a[1]), "r"(a[2]), "r"(a[3]), "r"(b[0]), "r"(b[1]));
}

// ---------------- spectral norm (fused across all 3 weights) ----------------
__global__ void sn_zero() {
    int t = threadIdx.x;
    for (int i = t; i < 2304; i += 256) { g_t1[i] = 0.f; g_t2[i] = 0.f; }
    if (t < 256) g_t3[t] = 0.f;
    if (t < 3) { g_nt2[t] = 0.f; g_ns2[t] = 0.f; }
}

// grid (9, 8, 3): x = K tile, y = H chunk, z = weight select
__global__ void sn_tk_all(const float* __restrict__ w1, const float* __restrict__ u1,
                          const float* __restrict__ w2, const float* __restrict__ u2,
                          const float* __restrict__ ws, const float* __restrict__ us) {
    const int wsel = blockIdx.z;
    const float* W = (wsel == 0) ? w1 : (wsel == 1) ? w2 : ws;
    const float* u = (wsel == 0) ? u1 : (wsel == 1) ? u2 : us;
    float* t = (wsel == 0) ? g_t1 : (wsel == 1) ? g_t2 : g_t3;
    const int H = (wsel == 0) ? 256 : 512;
    const int K = (wsel == 2) ? 256 : 2304;
    int j = blockIdx.x * 256 + threadIdx.x;
    if (j >= K) return;
    int chunk = H >> 3;
    int i0 = blockIdx.y * chunk;
    int i1 = i0 + chunk;
    float s = 0.f;
    for (int i = i0; i < i1; i++)
        s = fmaf(W[(size_t)i * K + j], __ldg(u + i), s);
    atomicAdd(t + j, s);
}

// grid (512, 3): x = row, y = weight select
__global__ void sn_sk_all(const float* __restrict__ w1, const float* __restrict__ w2,
                          const float* __restrict__ ws) {
    const int wsel = blockIdx.y;
    const float* W = (wsel == 0) ? w1 : (wsel == 1) ? w2 : ws;
    const float* t = (wsel == 0) ? g_t1 : (wsel == 1) ? g_t2 : g_t3;
    const int H = (wsel == 0) ? 256 : 512;
    const int K = (wsel == 2) ? 256 : 2304;
    const int i = blockIdx.x;
    if (i >= H) return;  // uniform per block
    float s = 0.f;
    for (int j = threadIdx.x; j < K; j += blockDim.x)
        s = fmaf(W[(size_t)i * K + j], __ldg(t + j), s);
    s = block_sum(s);
    if (threadIdx.x == 0) atomicAdd(&g_ns2[wsel], s * s);
    if (i == 0) {
        float a = 0.f;
        for (int j = threadIdx.x; j < K; j += blockDim.x) {
            float tv = __ldg(t + j);
            a = fmaf(tv, tv, a);
        }
        a = block_sum(a);
        if (threadIdx.x == 0) atomicAdd(&g_nt2[wsel], a);
    }
}

// single grid over all three weights (range-partitioned)
#define PREP_N1 (256 * 2304)
#define PREP_N2 (512 * 2304)
#define PREP_NS (512 * 256)
#define PREP_TOTAL (PREP_N1 + PREP_N2 + PREP_NS)

__global__ void prep_all(const float* __restrict__ w1, const float* __restrict__ w2,
                         const float* __restrict__ ws) {
    int idx = blockIdx.x * blockDim.x + threadIdx.x;
    if (idx >= PREP_TOTAL) return;
    const float* w;
    __half* wt;
    int sigIdx, KHW, li;
    float extra;
    if (idx < PREP_N1) {
        w = w1; wt = g_wt1; sigIdx = 0; KHW = 9; li = idx; extra = 1.f;
    } else if (idx < PREP_N1 + PREP_N2) {
        w = w2; wt = g_wt2; sigIdx = 1; KHW = 9; li = idx - PREP_N1; extra = 1.f;
    } else {
        w = ws; wt = g_wts; sigIdx = 2; KHW = 1; li = idx - PREP_N1 - PREP_N2; extra = RSQRT2;
    }
    float nt = sqrtf(g_nt2[sigIdx]);
    float nwt = sqrtf(g_ns2[sigIdx]);
    float nwv = nwt / (nt + 1e-12f);
    float sigma = nwv * nwv / (nwv + 1e-12f);
    int khw = li % KHW;
    int t = li / KHW;
    int ic = t & 255;
    int oc = t >> 8;
    float v = w[li] * (extra / sigma);
    wt[((size_t)oc * KHW + khw) * 256 + ic] = __float2half_rn(v);
}

// ---------------- input prep ----------------
__global__ void zero_halo(__half* xp) {
    int i = blockIdx.x * blockDim.x + threadIdx.x;
    const int per = 260 * 32;
    if (i >= 16 * per) return;
    int img = i / per;
    int r = i - img * per;
    int pix = r >> 5, q = r & 31;
    int h, w;
    if (pix < 66) { h = 0; w = pix; }
    else if (pix < 132) { h = 65; w = pix - 66; }
    else if (pix < 196) { h = pix - 131; w = 0; }
    else { h = pix - 195; w = 65; }
    reinterpret_cast<int4*>(xp + (((size_t)img * 66 + h) * 66 + w) * 256)[q] =
        make_int4(0, 0, 0, 0);
}

__global__ void pad_x_t(const float* __restrict__ x, __half* __restrict__ xp) {
    __shared__ float sm[64][33];
    const int wt = blockIdx.x;
    const int ict = blockIdx.y;
    const int plane = blockIdx.z;
    const int img = plane >> 6, h = plane & 63;
    const int w0 = wt * 32, ic0 = ict * 64;
    const int tid = threadIdx.x;
    const int icl = tid >> 5, wl = tid & 31;
    const float* xb = x + (((size_t)img * 256 + ic0) * 64 + h) * 64 + w0;
#pragma unroll
    for (int r = 0; r < 8; r++)
        sm[icl + r * 8][wl] = xb[(size_t)(icl + r * 8) * 4096 + wl];
    __syncthreads();
    const int wIdx = tid >> 3, icq = tid & 7;
    __half hv[8];
#pragma unroll
    for (int k = 0; k < 8; k++) hv[k] = __float2half_rn(sm[icq * 8 + k][wIdx]);
    *reinterpret_cast<int4*>(
        xp + (((size_t)img * 66 + h + 1) * 66 + (w0 + wIdx + 1)) * 256 + ic0 + icq * 8) =
        *reinterpret_cast<int4*>(hv);
}

// ---------------- 4x4 binomial blur, NHWC, 8ch/thread ----------------
template <bool CHECK, int OFF>
__global__ void blur_nhwc(const __half* __restrict__ in, __half* __restrict__ out,
                          int inW, int outW) {
    int idx = blockIdx.x * blockDim.x + threadIdx.x;
    int total = 16 * outW * outW * 32;
    if (idx >= total) return;
    const int icq = idx & 31;
    int t = idx >> 5;
    const int x = t % outW; t /= outW;
    const int y = t % outW;
    const int img = t / outW;
    const __half* ib = in + (size_t)img * inW * inW * 256 + icq * 8;
    float acc[8];
#pragma unroll
    for (int q = 0; q < 8; q++) acc[q] = 0.f;
    const float kv[4] = {1.f, 3.f, 3.f, 1.f};
#pragma unroll
    for (int i = 0; i < 4; i++) {
        int yy = y + i + OFF;
        if (CHECK && ((unsigned)yy >= (unsigned)inW)) continue;
#pragma unroll
        for (int j = 0; j < 4; j++) {
            int xx = x + j + OFF;
            if (CHECK && ((unsigned)xx >= (unsigned)inW)) continue;
            int4 v = *reinterpret_cast<const int4*>(ib + ((size_t)yy * inW + xx) * 256);
            const __half* h = reinterpret_cast<const __half*>(&v);
            float w = kv[i] * kv[j];
#pragma unroll
            for (int q = 0; q < 8; q++) acc[q] = fmaf(w, __half2float(h[q]), acc[q]);
        }
    }
    __half res[8];
#pragma unroll
    for (int q = 0; q < 8; q++) res[q] = __float2half_rn(acc[q] * (1.f / 64.f));
    *reinterpret_cast<int4*>(
        out + ((size_t)img * outW * outW + (size_t)y * outW + x) * 256 + icq * 8) =
        *reinterpret_cast<int4*>(res);
}

// ---------------------------------------------------------------------------
// fp16 mma.sync implicit-GEMM conv, NHWC, cp.async 3-stage ring (2 in flight).
// ---------------------------------------------------------------------------
#define STAGE_BYTES 20480
#define CONV_SMEM (3 * STAGE_BYTES)

template <int KHW, int STRIDE, int EPI>
__global__ void __launch_bounds__(256, 2) conv_hmma(
    const __half* __restrict__ in, const __half* __restrict__ wt,
    const float* __restrict__ bias, void* __restrict__ outv,
    int INROW, int INIMG, int OC, int OH, int OW, int NS) {
    extern __shared__ char smem[];
    const uint32_t sb = smem_u32(smem);

    const int tid = threadIdx.x;
    const int lane = tid & 31;
    const int wid = tid >> 5;
    const int wm = wid & 3;
    const int wn = wid >> 2;

    const int m0 = blockIdx.x * 128;
    const int ocb = blockIdx.y * 128;
    const int ohw = OH * OW;
    const int img = m0 / ohw;
    const int rbase = m0 - img * ohw;

    const int mIdx = tid >> 1;
    const int kq = tid & 1;
    const int m = rbase + mIdx;
    const int oh = m / OW;
    const int ow = m - oh * OW;
    const __half* abase = in + (size_t)img * INIMG + (size_t)(oh * STRIDE) * INROW +
                          (size_t)(ow * STRIDE) * 256 + kq * 16;
    const __half* bbase = wt + (size_t)(ocb + mIdx) * KHW * 256 + kq * 16;
    const uint32_t stsOff = (uint32_t)(mIdx * 80 + kq * 32);

    const int lg = lane >> 3, lr = lane & 7;
    const uint32_t rowsel = (uint32_t)(lr + ((lg >> 1) << 3));
    const uint32_t kcol = (uint32_t)((lg & 1) << 4);
    const uint32_t aLMr = (wm * 32 + rowsel) * 80 + kcol;
    const uint32_t bLMr = (wn * 64 + rowsel) * 80 + kcol;

    float c[2][8][4];
#pragma unroll
    for (int mb = 0; mb < 2; mb++)
#pragma unroll
        for (int nb = 0; nb < 8; nb++)
#pragma unroll
            for (int q = 0; q < 4; q++) c[mb][nb][q] = 0.f;

    auto CPA = [&](int s, uint32_t base) {
        const int kk = s * 32;
        const int khw = (KHW == 1) ? 0 : (kk >> 8);
        const int ic0 = kk - (khw << 8);
        int kh = 0, kw = 0;
        if (KHW == 9) { kh = khw / 3; kw = khw - kh * 3; }
        const __half* ap = abase + (size_t)kh * INROW + kw * 256 + ic0;
        cpa16(base + stsOff, ap);
        cpa16(base + stsOff + 16, ap + 8);
        const __half* bp = bbase + khw * 256 + ic0;
        cpa16(base + 10240 + stsOff, bp);
        cpa16(base + 10240 + stsOff + 16, bp + 8);
        cp_commit();
    };

    auto MMA = [&](uint32_t base) {
        const uint32_t aLM = base + aLMr;
        const uint32_t bLM = base + 10240 + bLMr;
#pragma unroll
        for (int k16 = 0; k16 < 2; k16++) {
            uint32_t a[2][4], b[8][2];
#pragma unroll
            for (int mb = 0; mb < 2; mb++) {
                uint32_t r[4];
                ldsm4(r, aLM + k16 * 32 + mb * 1280);
                a[mb][0] = r[0]; a[mb][1] = r[2]; a[mb][2] = r[1]; a[mb][3] = r[3];
            }
#pragma unroll
            for (int nbp = 0; nbp < 4; nbp++) {
                uint32_t r[4];
                ldsm4(r, bLM + k16 * 32 + nbp * 1280);
                b[nbp * 2][0] = r[0]; b[nbp * 2][1] = r[1];
                b[nbp * 2 + 1][0] = r[2]; b[nbp * 2 + 1][1] = r[3];
            }
#pragma unroll
            for (int mb = 0; mb < 2; mb++)
#pragma unroll
                for (int nb = 0; nb < 8; nb++)
                    mma16816(c[mb][nb], a[mb], b[nb]);
        }
    };

    CPA(0, sb);
    if (NS > 1) CPA(1, sb + STAGE_BYTES);
    int ring = 0;
    for (int s = 0; s < NS; s++) {
        if (s + 1 < NS) cp_wait<1>(); else cp_wait<0>();
        __syncthreads();
        const uint32_t cur = sb + ring * STAGE_BYTES;
        if (s + 2 < NS) {
            int nxt = ring + 2; if (nxt >= 3) nxt -= 3;
            CPA(s + 2, sb + nxt * STAGE_BYTES);
        }
        MMA(cur);
        ring = (ring == 2) ? 0 : ring + 1;
    }
    __syncthreads();

    const int erow = lane >> 2;
    const int ecolp = (lane & 3) * 2;

    if (EPI == 0) {
        __half* ob = (__half*)outv;
#pragma unroll
        for (int mb = 0; mb < 2; mb++) {
            const size_t mrow = (size_t)(m0 + wm * 32 + mb * 16 + erow);
#pragma unroll
            for (int nb = 0; nb < 8; nb++) {
                const int col = ocb + wn * 64 + nb * 8 + ecolp;
                const float bv0 = __ldg(bias + col);
                const float bv1 = __ldg(bias + col + 1);
                const float* cc = c[mb][nb];
                float v0 = cc[0] + bv0, v1 = cc[1] + bv1;
                float v2 = cc[2] + bv0, v3 = cc[3] + bv1;
                v0 = v0 > 0.f ? v0 : 0.2f * v0;
                v1 = v1 > 0.f ? v1 : 0.2f * v1;
                v2 = v2 > 0.f ? v2 : 0.2f * v2;
                v3 = v3 > 0.f ? v3 : 0.2f * v3;
                __half2 h0 = __floats2half2_rn(v0, v1);
                __half2 h1 = __floats2half2_rn(v2, v3);
                *reinterpret_cast<__half2*>(ob + mrow * 256 + col) = h0;
                *reinterpret_cast<__half2*>(ob + (mrow + 8) * 256 + col) = h1;
            }
        }
    } else {
        for (int nc = 0; nc < 4; nc++) {
            if (wn == (nc >> 1)) {
                const int nbBase = (nc & 1) * 4;
#pragma unroll
                for (int mb = 0; mb < 2; mb++) {
                    const int mrow = wm * 32 + mb * 16 + erow;
#pragma unroll
                    for (int j = 0; j < 4; j++) {
                        const int nb = nbBase + j;
                        const int ocl = j * 8 + ecolp;
                        const float* cc = c[mb][nb];
                        sts32f(sb + (uint32_t)(ocl * 544 + mrow * 4), cc[0]);
                        sts32f(sb + (uint32_t)((ocl + 1) * 544 + mrow * 4), cc[1]);
                        sts32f(sb + (uint32_t)(ocl * 544 + (mrow + 8) * 4), cc[2]);
                        sts32f(sb + (uint32_t)((ocl + 1) * 544 + (mrow + 8) * 4), cc[3]);
                    }
                }
            }
            __syncthreads();
#pragma unroll
            for (int p = 0; p < 4; p++) {
                const int idx = p * 256 + tid;
                const int ocl = idx >> 5;
                const int mq = (idx & 31) * 4;
                float4 v = lds128f(sb + (uint32_t)(ocl * 544 + mq * 4));
                const int oc = ocb + nc * 32 + ocl;
                const size_t go = ((size_t)img * OC + oc) * ohw + rbase + mq;
                if (EPI == 1) {
                    const float bv = __ldg(bias + oc);
                    v.x += bv; v.y += bv; v.z += bv; v.w += bv;
                    v.x = v.x > 0.f ? v.x : 0.2f * v.x;
                    v.y = v.y > 0.f ? v.y : 0.2f * v.y;
                    v.z = v.z > 0.f ? v.z : 0.2f * v.z;
                    v.w = v.w > 0.f ? v.w : 0.2f * v.w;
                    *reinterpret_cast<float4*>((float*)outv + go) = v;
                } else {
                    float* op = (float*)outv + go;
                    float4 o = *reinterpret_cast<const float4*>(op);
                    o.x = o.x * RSQRT2 + v.x;
                    o.y = o.y * RSQRT2 + v.y;
                    o.z = o.z * RSQRT2 + v.z;
                    o.w = o.w * RSQRT2 + v.w;
                    *reinterpret_cast<float4*>(op) = o;
                }
            }
            __syncthreads();
        }
    }
}

// ---------------------------------------------------------------------------
extern "C" void kernel_launch(void* const* d_in, const int* in_sizes, int n_in,
                              void* d_out, int out_size) {
    const float* x   = (const float*)d_in[0];
    const float* w1  = (const float*)d_in[1];
    const float* u1  = (const float*)d_in[2];
    const float* b1  = (const float*)d_in[4];
    const float* w2  = (const float*)d_in[5];
    const float* u2  = (const float*)d_in[6];
    const float* b2  = (const float*)d_in[8];
    const float* wsk = (const float*)d_in[9];
    const float* us  = (const float*)d_in[10];
    float* out = (float*)d_out;

    __half *xpad, *bufA, *bufB, *bufC, *wt1, *wt2, *wts;
    cudaGetSymbolAddress((void**)&xpad, g_xpad);
    cudaGetSymbolAddress((void**)&bufA, g_bufA);
    cudaGetSymbolAddress((void**)&bufB, g_bufB);
    cudaGetSymbolAddress((void**)&bufC, g_bufC);
    cudaGetSymbolAddress((void**)&wt1, g_wt1);
    cudaGetSymbolAddress((void**)&wt2, g_wt2);
    cudaGetSymbolAddress((void**)&wts, g_wts);

    cudaFuncSetAttribute(conv_hmma<9, 1, 0>,
                         cudaFuncAttributeMaxDynamicSharedMemorySize, CONV_SMEM);
    cudaFuncSetAttribute(conv_hmma<9, 2, 1>,
                         cudaFuncAttributeMaxDynamicSharedMemorySize, CONV_SMEM);
    cudaFuncSetAttribute(conv_hmma<1, 2, 2>,
                         cudaFuncAttributeMaxDynamicSharedMemorySize, CONV_SMEM);

    // ---- fused SN for all three weights (4 launches total) ----
    sn_zero<<<1, 256>>>();
    sn_tk_all<<<dim3(9, 8, 3), 256>>>(w1, u1, w2, u2, wsk, us);
    sn_sk_all<<<dim3(512, 3), 256>>>(w1, w2, wsk);
    prep_all<<<(PREP_TOTAL + 255) / 256, 256>>>(w1, w2, wsk);

    // ---- input prep: halo zero + NCHW->NHWC transpose ----
    {
        const int n = 16 * 260 * 32;
        zero_halo<<<(n + 255) / 256, 256>>>(xpad);
        pad_x_t<<<dim3(2, 4, 16 * 64), 256>>>(x, xpad);
    }

    // ---- conv1: xpad -> bufA NHWC [16,64,64,256], bias+lrelu ----
    conv_hmma<9, 1, 0><<<dim3(512, 2), 256, CONV_SMEM>>>(
        xpad, wt1, b1, bufA, 66 * 256, 66 * 66 * 256, 256, 64, 64, 72);

    // ---- blurs ----
    {
        const int t = 16 * 63 * 63 * 32;
        blur_nhwc<false, 0><<<(t + 255) / 256, 256>>>(xpad, bufB, 66, 63);
    }
    {
        const int t = 16 * 65 * 65 * 32;
        blur_nhwc<true, -2><<<(t + 255) / 256, 256>>>(bufA, bufC, 64, 65);
    }

    // ---- conv2 -> out NCHW f32 ----
    conv_hmma<9, 2, 1><<<dim3(128, 4), 256, CONV_SMEM>>>(
        bufC, wt2, b2, out, 65 * 256, 65 * 65 * 256, 512, 32, 32, 72);

    // ---- skip conv: out = out*rsqrt2 + acc (rsqrt2 folded in wts) ----
    conv_hmma<1, 2, 2><<<dim3(128, 4), 256, CONV_SMEM>>>(
        bufB, wts, nullptr, out, 63 * 256, 63 * 63 * 256, 512, 32, 32, 8);
}

// round 11
// speedup vs baseline: 7.1928x; 1.0037x over previous
#include <cuda_runtime.h>
#include <cuda_fp16.h>
#include <math.h>
#include <stdint.h>

#define RSQRT2 0.70710678118654752f

// ---------------- device scratch (allocation-free rule) ----------------
// NOTE: BSS zero-init is load-time state. g_t*/g_nt2/g_ns2 are re-zeroed at the
// END of every kernel_launch (graph tail), so each replay starts from zeros.
// xpad's halo is never written by any kernel and stays zero forever.
__device__ float g_t1[2304];
__device__ float g_t2[2304];
__device__ float g_t3[256];
__device__ float g_nt2[3];
__device__ float g_ns2[3];
__device__ __half g_xpad[16 * 66 * 66 * 256];   // NHWC padded fp16 x (halo always 0)
__device__ __half g_bufA[16 * 64 * 64 * 256];   // conv1 output NHWC
__device__ __half g_bufB[16 * 63 * 63 * 256];   // blur(x,pad1) NHWC
__device__ __half g_bufC[16 * 65 * 65 * 256];   // blur(conv1,pad2) NHWC
__device__ __half g_wt1[256 * 9 * 256];         // [oc][khw][ic]  (unscaled fp16)
__device__ __half g_wt2[512 * 9 * 256];
__device__ __half g_wts[512 * 256];

// ---------------- helpers ----------------
__device__ __forceinline__ float warp_sum(float v) {
#pragma unroll
    for (int o = 16; o; o >>= 1) v += __shfl_down_sync(0xffffffffu, v, o);
    return v;
}

__device__ float block_sum(float v) {
    __shared__ float red[32];
    int lane = threadIdx.x & 31, w = threadIdx.x >> 5;
    v = warp_sum(v);
    if (lane == 0) red[w] = v;
    __syncthreads();
    float r = 0.f;
    if (w == 0) {
        int nw = (blockDim.x + 31) >> 5;
        r = (lane < nw) ? red[lane] : 0.f;
        r = warp_sum(r);
    }
    __syncthreads();
    return r;
}

__device__ __forceinline__ uint32_t smem_u32(const void* p) {
    uint32_t a;
    asm("{ .reg .u64 t; cvta.to.shared.u64 t, %1; cvt.u32.u64 %0, t; }" : "=r"(a) : "l"(p));
    return a;
}

__device__ __forceinline__ void sts32f(uint32_t a, float v) {
    asm volatile("st.shared.b32 [%0], %1;" :: "r"(a), "f"(v) : "memory");
}
__device__ __forceinline__ float4 lds128f(uint32_t a) {
    float4 v;
    asm volatile("ld.shared.v4.f32 {%0,%1,%2,%3}, [%4];"
                 : "=f"(v.x), "=f"(v.y), "=f"(v.z), "=f"(v.w) : "r"(a));
    return v;
}

__device__ __forceinline__ void cpa16(uint32_t s, const void* g) {
    asm volatile("cp.async.cg.shared.global [%0], [%1], 16;" :: "r"(s), "l"(g) : "memory");
}
__device__ __forceinline__ void cp_commit() {
    asm volatile("cp.async.commit_group;" ::: "memory");
}
template <int N>
__device__ __forceinline__ void cp_wait() {
    asm volatile("cp.async.wait_group %0;" :: "n"(N) : "memory");
}

__device__ __forceinline__ void ldsm4(uint32_t* r, uint32_t addr) {
    asm volatile("ldmatrix.sync.aligned.m8n8.x4.shared.b16 {%0,%1,%2,%3}, [%4];"
                 : "=r"(r[0]), "=r"(r[1]), "=r"(r[2]), "=r"(r[3]) : "r"(addr));
}

__device__ __forceinline__ void mma16816(float* c, const uint32_t* a, const uint32_t* b) {
    asm volatile(
        "mma.sync.aligned.m16n8k16.row.col.f32.f16.f16.f32 "
        "{%0,%1,%2,%3}, {%4,%5,%6,%7}, {%8,%9}, {%0,%1,%2,%3};"
        : "+f"(c[0]), "+f"(c[1]), "+f"(c[2]), "+f"(c[3])
        : "r"(a[0]), "r"(a[1]), "r"(a[2]), "r"(a[3]), "r"(b[0]), "r"(b[1]));
}

// inv_sigma from the accumulated norms (per conv epilogue, cheap)
__device__ __forceinline__ float inv_sigma_of(int sigIdx) {
    float nt = sqrtf(g_nt2[sigIdx]);
    float nwt = sqrtf(g_ns2[sigIdx]);
    float nwv = nwt / (nt + 1e-12f);
    return (nwv + 1e-12f) / (nwv * nwv);
}

// ---------------- spectral norm (fused across all 3 weights) ----------------
// grid (9, 8, 3): x = K tile, y = H chunk, z = weight select
__global__ void sn_tk_all(const float* __restrict__ w1, const float* __restrict__ u1,
                          const float* __restrict__ w2, const float* __restrict__ u2,
                          const float* __restrict__ ws, const float* __restrict__ us) {
    const int wsel = blockIdx.z;
    const float* W = (wsel == 0) ? w1 : (wsel == 1) ? w2 : ws;
    const float* u = (wsel == 0) ? u1 : (wsel == 1) ? u2 : us;
    float* t = (wsel == 0) ? g_t1 : (wsel == 1) ? g_t2 : g_t3;
    const int H = (wsel == 0) ? 256 : 512;
    const int K = (wsel == 2) ? 256 : 2304;
    int j = blockIdx.x * 256 + threadIdx.x;
    if (j >= K) return;
    int chunk = H >> 3;
    int i0 = blockIdx.y * chunk;
    int i1 = i0 + chunk;
    float s = 0.f;
    for (int i = i0; i < i1; i++)
        s = fmaf(W[(size_t)i * K + j], __ldg(u + i), s);
    atomicAdd(t + j, s);
}

// grid (512, 3): x = row, y = weight select
__global__ void sn_sk_all(const float* __restrict__ w1, const float* __restrict__ w2,
                          const float* __restrict__ ws) {
    const int wsel = blockIdx.y;
    const float* W = (wsel == 0) ? w1 : (wsel == 1) ? w2 : ws;
    const float* t = (wsel == 0) ? g_t1 : (wsel == 1) ? g_t2 : g_t3;
    const int H = (wsel == 0) ? 256 : 512;
    const int K = (wsel == 2) ? 256 : 2304;
    const int i = blockIdx.x;
    if (i >= H) return;
    float s = 0.f;
    for (int j = threadIdx.x; j < K; j += blockDim.x)
        s = fmaf(W[(size_t)i * K + j], __ldg(t + j), s);
    s = block_sum(s);
    if (threadIdx.x == 0) atomicAdd(&g_ns2[wsel], s * s);
    if (i == 0) {
        float a = 0.f;
        for (int j = threadIdx.x; j < K; j += blockDim.x) {
            float tv = __ldg(t + j);
            a = fmaf(tv, tv, a);
        }
        a = block_sum(a);
        if (threadIdx.x == 0) atomicAdd(&g_nt2[wsel], a);
    }
}

// graph tail: reset accumulators for the next replay
__global__ void sn_zero_tail() {
    int t = threadIdx.x;
    for (int i = t; i < 2304; i += 256) { g_t1[i] = 0.f; g_t2[i] = 0.f; }
    if (t < 256) g_t3[t] = 0.f;
    if (t < 3) { g_nt2[t] = 0.f; g_ns2[t] = 0.f; }
}

// ---------------- merged pad (NCHW f32 -> padded NHWC fp16) + weight prep ----
#define PAD_BLOCKS 8192               // (2 w-tiles) * (4 ic-tiles) * (16*64 planes)
#define PREP_N1 (256 * 256 * 9)
#define PREP_N2 (512 * 256 * 9)
#define PREP_NS (512 * 256)
#define PREP_TOTAL (PREP_N1 + PREP_N2 + PREP_NS)
#define PREP_BLOCKS ((PREP_TOTAL + 255) / 256)
#define PADPREP_BLOCKS (PAD_BLOCKS + PREP_BLOCKS)

__global__ void padprep(const float* __restrict__ x, __half* __restrict__ xp,
                        const float* __restrict__ w1, const float* __restrict__ w2,
                        const float* __restrict__ ws) {
    __shared__ float sm[64][33];
    const int bid = blockIdx.x;
    const int tid = threadIdx.x;
    if (bid < PAD_BLOCKS) {
        // pad: interior transpose x[img,ic,h,w] -> xp[img,h+1,w+1,ic]
        const int wt = bid & 1;
        const int ict = (bid >> 1) & 3;
        const int plane = bid >> 3;            // img*64 + h
        const int img = plane >> 6, h = plane & 63;
        const int w0 = wt * 32, ic0 = ict * 64;
        const int icl = tid >> 5, wl = tid & 31;
        const float* xb = x + (((size_t)img * 256 + ic0) * 64 + h) * 64 + w0;
#pragma unroll
        for (int r = 0; r < 8; r++)
            sm[icl + r * 8][wl] = xb[(size_t)(icl + r * 8) * 4096 + wl];
        __syncthreads();
        const int wIdx = tid >> 3, icq = tid & 7;
        __half hv[8];
#pragma unroll
        for (int k = 0; k < 8; k++) hv[k] = __float2half_rn(sm[icq * 8 + k][wIdx]);
        *reinterpret_cast<int4*>(
            xp + (((size_t)img * 66 + h + 1) * 66 + (w0 + wIdx + 1)) * 256 + ic0 + icq * 8) =
            *reinterpret_cast<int4*>(hv);
    } else {
        // prep: transpose/convert weights, NO sigma (folded into conv epilogue)
        int idx = (bid - PAD_BLOCKS) * 256 + tid;
        if (idx >= PREP_TOTAL) return;
        const float* w;
        __half* wtp;
        int KHW, li;
        if (idx < PREP_N1) {
            w = w1; wtp = g_wt1; KHW = 9; li = idx;
        } else if (idx < PREP_N1 + PREP_N2) {
            w = w2; wtp = g_wt2; KHW = 9; li = idx - PREP_N1;
        } else {
            w = ws; wtp = g_wts; KHW = 1; li = idx - PREP_N1 - PREP_N2;
        }
        int khw = li % KHW;
        int t = li / KHW;
        int ic = t & 255;
        int oc = t >> 8;
        wtp[((size_t)oc * KHW + khw) * 256 + ic] = __float2half_rn(w[li]);
    }
}

// ---------------- 4x4 binomial blur, NHWC, 8ch/thread ----------------
template <bool CHECK, int OFF>
__global__ void blur_nhwc(const __half* __restrict__ in, __half* __restrict__ out,
                          int inW, int outW) {
    int idx = blockIdx.x * blockDim.x + threadIdx.x;
    int total = 16 * outW * outW * 32;
    if (idx >= total) return;
    const int icq = idx & 31;
    int t = idx >> 5;
    const int x = t % outW; t /= outW;
    const int y = t % outW;
    const int img = t / outW;
    const __half* ib = in + (size_t)img * inW * inW * 256 + icq * 8;
    float acc[8];
#pragma unroll
    for (int q = 0; q < 8; q++) acc[q] = 0.f;
    const float kv[4] = {1.f, 3.f, 3.f, 1.f};
#pragma unroll
    for (int i = 0; i < 4; i++) {
        int yy = y + i + OFF;
        if (CHECK && ((unsigned)yy >= (unsigned)inW)) continue;
#pragma unroll
        for (int j = 0; j < 4; j++) {
            int xx = x + j + OFF;
            if (CHECK && ((unsigned)xx >= (unsigned)inW)) continue;
            int4 v = *reinterpret_cast<const int4*>(ib + ((size_t)yy * inW + xx) * 256);
            const __half* h = reinterpret_cast<const __half*>(&v);
            float w = kv[i] * kv[j];
#pragma unroll
            for (int q = 0; q < 8; q++) acc[q] = fmaf(w, __half2float(h[q]), acc[q]);
        }
    }
    __half res[8];
#pragma unroll
    for (int q = 0; q < 8; q++) res[q] = __float2half_rn(acc[q] * (1.f / 64.f));
    *reinterpret_cast<int4*>(
        out + ((size_t)img * outW * outW + (size_t)y * outW + x) * 256 + icq * 8) =
        *reinterpret_cast<int4*>(res);
}

// ---------------------------------------------------------------------------
// fp16 mma.sync implicit-GEMM conv, NHWC, cp.async 3-stage ring (2 in flight).
// inv_sigma applied in the epilogue (weights stored unscaled).
// EPI: 0 = *is + bias, lrelu -> NHWC fp16
//      1 = *is + bias, lrelu -> NCHW f32
//      2 = out*rsqrt2 + acc*is*rsqrt2 -> NCHW f32
// ---------------------------------------------------------------------------
#define STAGE_BYTES 20480
#define CONV_SMEM (3 * STAGE_BYTES)

template <int KHW, int STRIDE, int EPI>
__global__ void __launch_bounds__(256, 2) conv_hmma(
    const __half* __restrict__ in, const __half* __restrict__ wt,
    const float* __restrict__ bias, void* __restrict__ outv,
    int INROW, int INIMG, int OC, int OH, int OW, int NS, int sigIdx) {
    extern __shared__ char smem[];
    const uint32_t sb = smem_u32(smem);

    const int tid = threadIdx.x;
    const int lane = tid & 31;
    const int wid = tid >> 5;
    const int wm = wid & 3;
    const int wn = wid >> 2;

    const int m0 = blockIdx.x * 128;
    const int ocb = blockIdx.y * 128;
    const int ohw = OH * OW;
    const int img = m0 / ohw;
    const int rbase = m0 - img * ohw;

    const int mIdx = tid >> 1;
    const int kq = tid & 1;
    const int m = rbase + mIdx;
    const int oh = m / OW;
    const int ow = m - oh * OW;
    const __half* abase = in + (size_t)img * INIMG + (size_t)(oh * STRIDE) * INROW +
                          (size_t)(ow * STRIDE) * 256 + kq * 16;
    const __half* bbase = wt + (size_t)(ocb + mIdx) * KHW * 256 + kq * 16;
    const uint32_t stsOff = (uint32_t)(mIdx * 80 + kq * 32);

    const int lg = lane >> 3, lr = lane & 7;
    const uint32_t rowsel = (uint32_t)(lr + ((lg >> 1) << 3));
    const uint32_t kcol = (uint32_t)((lg & 1) << 4);
    const uint32_t aLMr = (wm * 32 + rowsel) * 80 + kcol;
    const uint32_t bLMr = (wn * 64 + rowsel) * 80 + kcol;

    float c[2][8][4];
#pragma unroll
    for (int mb = 0; mb < 2; mb++)
#pragma unroll
        for (int nb = 0; nb < 8; nb++)
#pragma unroll
            for (int q = 0; q < 4; q++) c[mb][nb][q] = 0.f;

    auto CPA = [&](int s, uint32_t base) {
        const int kk = s * 32;
        const int khw = (KHW == 1) ? 0 : (kk >> 8);
        const int ic0 = kk - (khw << 8);
        int kh = 0, kw = 0;
        if (KHW == 9) { kh = khw / 3; kw = khw - kh * 3; }
        const __half* ap = abase + (size_t)kh * INROW + kw * 256 + ic0;
        cpa16(base + stsOff, ap);
        cpa16(base + stsOff + 16, ap + 8);
        const __half* bp = bbase + khw * 256 + ic0;
        cpa16(base + 10240 + stsOff, bp);
        cpa16(base + 10240 + stsOff + 16, bp + 8);
        cp_commit();
    };

    auto MMA = [&](uint32_t base) {
        const uint32_t aLM = base + aLMr;
        const uint32_t bLM = base + 10240 + bLMr;
#pragma unroll
        for (int k16 = 0; k16 < 2; k16++) {
            uint32_t a[2][4], b[8][2];
#pragma unroll
            for (int mb = 0; mb < 2; mb++) {
                uint32_t r[4];
                ldsm4(r, aLM + k16 * 32 + mb * 1280);
                a[mb][0] = r[0]; a[mb][1] = r[2]; a[mb][2] = r[1]; a[mb][3] = r[3];
            }
#pragma unroll
            for (int nbp = 0; nbp < 4; nbp++) {
                uint32_t r[4];
                ldsm4(r, bLM + k16 * 32 + nbp * 1280);
                b[nbp * 2][0] = r[0]; b[nbp * 2][1] = r[1];
                b[nbp * 2 + 1][0] = r[2]; b[nbp * 2 + 1][1] = r[3];
            }
#pragma unroll
            for (int mb = 0; mb < 2; mb++)
#pragma unroll
                for (int nb = 0; nb < 8; nb++)
                    mma16816(c[mb][nb], a[mb], b[nb]);
        }
    };

    CPA(0, sb);
    if (NS > 1) CPA(1, sb + STAGE_BYTES);
    int ring = 0;
    for (int s = 0; s < NS; s++) {
        if (s + 1 < NS) cp_wait<1>(); else cp_wait<0>();
        __syncthreads();
        const uint32_t cur = sb + ring * STAGE_BYTES;
        if (s + 2 < NS) {
            int nxt = ring + 2; if (nxt >= 3) nxt -= 3;
            CPA(s + 2, sb + nxt * STAGE_BYTES);
        }
        MMA(cur);
        ring = (ring == 2) ? 0 : ring + 1;
    }
    __syncthreads();

    const float is = inv_sigma_of(sigIdx);
    const int erow = lane >> 2;
    const int ecolp = (lane & 3) * 2;

    if (EPI == 0) {
        __half* ob = (__half*)outv;
#pragma unroll
        for (int mb = 0; mb < 2; mb++) {
            const size_t mrow = (size_t)(m0 + wm * 32 + mb * 16 + erow);
#pragma unroll
            for (int nb = 0; nb < 8; nb++) {
                const int col = ocb + wn * 64 + nb * 8 + ecolp;
                const float bv0 = __ldg(bias + col);
                const float bv1 = __ldg(bias + col + 1);
                const float* cc = c[mb][nb];
                float v0 = fmaf(cc[0], is, bv0), v1 = fmaf(cc[1], is, bv1);
                float v2 = fmaf(cc[2], is, bv0), v3 = fmaf(cc[3], is, bv1);
                v0 = v0 > 0.f ? v0 : 0.2f * v0;
                v1 = v1 > 0.f ? v1 : 0.2f * v1;
                v2 = v2 > 0.f ? v2 : 0.2f * v2;
                v3 = v3 > 0.f ? v3 : 0.2f * v3;
                __half2 h0 = __floats2half2_rn(v0, v1);
                __half2 h1 = __floats2half2_rn(v2, v3);
                *reinterpret_cast<__half2*>(ob + mrow * 256 + col) = h0;
                *reinterpret_cast<__half2*>(ob + (mrow + 8) * 256 + col) = h1;
            }
        }
    } else {
        const float sc = is * RSQRT2;   // EPI 2 scale
        for (int nc = 0; nc < 4; nc++) {
            if (wn == (nc >> 1)) {
                const int nbBase = (nc & 1) * 4;
#pragma unroll
                for (int mb = 0; mb < 2; mb++) {
                    const int mrow = wm * 32 + mb * 16 + erow;
#pragma unroll
                    for (int j = 0; j < 4; j++) {
                        const int nb = nbBase + j;
                        const int ocl = j * 8 + ecolp;
                        const float* cc = c[mb][nb];
                        sts32f(sb + (uint32_t)(ocl * 544 + mrow * 4), cc[0]);
                        sts32f(sb + (uint32_t)((ocl + 1) * 544 + mrow * 4), cc[1]);
                        sts32f(sb + (uint32_t)(ocl * 544 + (mrow + 8) * 4), cc[2]);
                        sts32f(sb + (uint32_t)((ocl + 1) * 544 + (mrow + 8) * 4), cc[3]);
                    }
                }
            }
            __syncthreads();
#pragma unroll
            for (int p = 0; p < 4; p++) {
                const int idx = p * 256 + tid;
                const int ocl = idx >> 5;
                const int mq = (idx & 31) * 4;
                float4 v = lds128f(sb + (uint32_t)(ocl * 544 + mq * 4));
                const int oc = ocb + nc * 32 + ocl;
                const size_t go = ((size_t)img * OC + oc) * ohw + rbase + mq;
                if (EPI == 1) {
                    const float bv = __ldg(bias + oc);
                    v.x = fmaf(v.x, is, bv); v.y = fmaf(v.y, is, bv);
                    v.z = fmaf(v.z, is, bv); v.w = fmaf(v.w, is, bv);
                    v.x = v.x > 0.f ? v.x : 0.2f * v.x;
                    v.y = v.y > 0.f ? v.y : 0.2f * v.y;
                    v.z = v.z > 0.f ? v.z : 0.2f * v.z;
                    v.w = v.w > 0.f ? v.w : 0.2f * v.w;
                    *reinterpret_cast<float4*>((float*)outv + go) = v;
                } else {
                    float* op = (float*)outv + go;
                    float4 o = *reinterpret_cast<const float4*>(op);
                    o.x = fmaf(v.x, sc, o.x * RSQRT2);
                    o.y = fmaf(v.y, sc, o.y * RSQRT2);
                    o.z = fmaf(v.z, sc, o.z * RSQRT2);
                    o.w = fmaf(v.w, sc, o.w * RSQRT2);
                    *reinterpret_cast<float4*>(op) = o;
                }
            }
            __syncthreads();
        }
    }
}

// ---------------------------------------------------------------------------
extern "C" void kernel_launch(void* const* d_in, const int* in_sizes, int n_in,
                              void* d_out, int out_size) {
    const float* x   = (const float*)d_in[0];
    const float* w1  = (const float*)d_in[1];
    const float* u1  = (const float*)d_in[2];
    const float* b1  = (const float*)d_in[4];
    const float* w2  = (const float*)d_in[5];
    const float* u2  = (const float*)d_in[6];
    const float* b2  = (const float*)d_in[8];
    const float* wsk = (const float*)d_in[9];
    const float* us  = (const float*)d_in[10];
    float* out = (float*)d_out;

    __half *xpad, *bufA, *bufB, *bufC, *wt1, *wt2, *wts;
    cudaGetSymbolAddress((void**)&xpad, g_xpad);
    cudaGetSymbolAddress((void**)&bufA, g_bufA);
    cudaGetSymbolAddress((void**)&bufB, g_bufB);
    cudaGetSymbolAddress((void**)&bufC, g_bufC);
    cudaGetSymbolAddress((void**)&wt1, g_wt1);
    cudaGetSymbolAddress((void**)&wt2, g_wt2);
    cudaGetSymbolAddress((void**)&wts, g_wts);

    cudaFuncSetAttribute(conv_hmma<9, 1, 0>,
                         cudaFuncAttributeMaxDynamicSharedMemorySize, CONV_SMEM);
    cudaFuncSetAttribute(conv_hmma<9, 2, 1>,
                         cudaFuncAttributeMaxDynamicSharedMemorySize, CONV_SMEM);
    cudaFuncSetAttribute(conv_hmma<1, 2, 2>,
                         cudaFuncAttributeMaxDynamicSharedMemorySize, CONV_SMEM);

    // #0: t = W^T u  (atomics into g_t*, zeroed by previous run's tail / BSS)
    sn_tk_all<<<dim3(9, 8, 3), 256>>>(w1, u1, w2, u2, wsk, us);
    // #1: ||Wt||^2, ||t||^2
    sn_sk_all<<<dim3(512, 3), 256>>>(w1, w2, wsk);
    // #2: pad/transpose x + transpose/convert weights (sigma-free)
    padprep<<<PADPREP_BLOCKS, 256>>>(x, xpad, w1, w2, wsk);
    // #3: conv1 (ncu sampling slot)
    conv_hmma<9, 1, 0><<<dim3(512, 2), 256, CONV_SMEM>>>(
        xpad, wt1, b1, bufA, 66 * 256, 66 * 66 * 256, 256, 64, 64, 72, 0);
    // #4: blurB (skip path)
    {
        const int t = 16 * 63 * 63 * 32;
        blur_nhwc<false, 0><<<(t + 255) / 256, 256>>>(xpad, bufB, 66, 63);
    }
    // #5: blurC
    {
        const int t = 16 * 65 * 65 * 32;
        blur_nhwc<true, -2><<<(t + 255) / 256, 256>>>(bufA, bufC, 64, 65);
    }
    // #6: conv2 -> out NCHW f32
    conv_hmma<9, 2, 1><<<dim3(128, 4), 256, CONV_SMEM>>>(
        bufC, wt2, b2, out, 65 * 256, 65 * 65 * 256, 512, 32, 32, 72, 1);
    // #7: skip conv: out = out*rsqrt2 + acc*is*rsqrt2
    conv_hmma<1, 2, 2><<<dim3(128, 4), 256, CONV_SMEM>>>(
        bufB, wts, nullptr, out, 63 * 256, 63 * 63 * 256, 512, 32, 32, 8, 2);
    // #8: reset SN accumulators for the next replay
    sn_zero_tail<<<1, 256>>>();
}

// round 12
// speedup vs baseline: 7.2844x; 1.0127x over previous
#include <cuda_runtime.h>
#include <cuda_fp16.h>
#include <math.h>
#include <stdint.h>

#define RSQRT2 0.70710678118654752f

// ---------------- device scratch (allocation-free rule) ----------------
// BSS zero-init is load-time state. g_t*/g_nt2/g_ns2 are re-zeroed at the END
// of every kernel_launch (graph tail), so each replay starts from zeros.
// xpad's halo is never written by any kernel and stays zero forever.
__device__ float g_t1[2304];
__device__ float g_t2[2304];
__device__ float g_t3[256];
__device__ float g_nt2[3];
__device__ float g_ns2[3];
__device__ __half g_xpad[16 * 66 * 66 * 256];   // NHWC padded fp16 x (halo always 0)
__device__ __half g_bufA[16 * 64 * 64 * 256];   // conv1 output NHWC
__device__ __half g_bufB[16 * 63 * 63 * 256];   // blur(x,pad1) NHWC
__device__ __half g_bufC[16 * 65 * 65 * 256];   // blur(conv1,pad2) NHWC
__device__ __half g_wt1[256 * 9 * 256];         // [oc][khw][ic]  (unscaled fp16)
__device__ __half g_wt2[512 * 9 * 256];
__device__ __half g_wts[512 * 256];

// ---------------- helpers ----------------
__device__ __forceinline__ float warp_sum(float v) {
#pragma unroll
    for (int o = 16; o; o >>= 1) v += __shfl_down_sync(0xffffffffu, v, o);
    return v;
}

__device__ float block_sum(float v) {
    __shared__ float red[32];
    int lane = threadIdx.x & 31, w = threadIdx.x >> 5;
    v = warp_sum(v);
    if (lane == 0) red[w] = v;
    __syncthreads();
    float r = 0.f;
    if (w == 0) {
        int nw = (blockDim.x + 31) >> 5;
        r = (lane < nw) ? red[lane] : 0.f;
        r = warp_sum(r);
    }
    __syncthreads();
    return r;
}

__device__ __forceinline__ uint32_t smem_u32(const void* p) {
    uint32_t a;
    asm("{ .reg .u64 t; cvta.to.shared.u64 t, %1; cvt.u32.u64 %0, t; }" : "=r"(a) : "l"(p));
    return a;
}

__device__ __forceinline__ void sts32f(uint32_t a, float v) {
    asm volatile("st.shared.b32 [%0], %1;" :: "r"(a), "f"(v) : "memory");
}
__device__ __forceinline__ float4 lds128f(uint32_t a) {
    float4 v;
    asm volatile("ld.shared.v4.f32 {%0,%1,%2,%3}, [%4];"
                 : "=f"(v.x), "=f"(v.y), "=f"(v.z), "=f"(v.w) : "r"(a));
    return v;
}

__device__ __forceinline__ void cpa16(uint32_t s, const void* g) {
    asm volatile("cp.async.cg.shared.global [%0], [%1], 16;" :: "r"(s), "l"(g) : "memory");
}
__device__ __forceinline__ void cp_commit() {
    asm volatile("cp.async.commit_group;" ::: "memory");
}
template <int N>
__device__ __forceinline__ void cp_wait() {
    asm volatile("cp.async.wait_group %0;" :: "n"(N) : "memory");
}

__device__ __forceinline__ void ldsm4(uint32_t* r, uint32_t addr) {
    asm volatile("ldmatrix.sync.aligned.m8n8.x4.shared.b16 {%0,%1,%2,%3}, [%4];"
                 : "=r"(r[0]), "=r"(r[1]), "=r"(r[2]), "=r"(r[3]) : "r"(addr));
}

__device__ __forceinline__ void mma16816(float* c, const uint32_t* a, const uint32_t* b) {
    asm volatile(
        "mma.sync.aligned.m16n8k16.row.col.f32.f16.f16.f32 "
        "{%0,%1,%2,%3}, {%4,%5,%6,%7}, {%8,%9}, {%0,%1,%2,%3};"
        : "+f"(c[0]), "+f"(c[1]), "+f"(c[2]), "+f"(c[3])
        : "r"(a[0]), "r"(a[1]), "r"(a[2]), "r"(a[3]), "r"(b[0]), "r"(b[1]));
}

__device__ __forceinline__ float inv_sigma_of(int sigIdx) {
    float nt = sqrtf(g_nt2[sigIdx]);
    float nwt = sqrtf(g_ns2[sigIdx]);
    float nwv = nwt / (nt + 1e-12f);
    return (nwv + 1e-12f) / (nwv * nwv);
}

// ---------------- spectral norm (fused across all 3 weights) ----------------
__global__ void sn_tk_all(const float* __restrict__ w1, const float* __restrict__ u1,
                          const float* __restrict__ w2, const float* __restrict__ u2,
                          const float* __restrict__ ws, const float* __restrict__ us) {
    const int wsel = blockIdx.z;
    const float* W = (wsel == 0) ? w1 : (wsel == 1) ? w2 : ws;
    const float* u = (wsel == 0) ? u1 : (wsel == 1) ? u2 : us;
    float* t = (wsel == 0) ? g_t1 : (wsel == 1) ? g_t2 : g_t3;
    const int H = (wsel == 0) ? 256 : 512;
    const int K = (wsel == 2) ? 256 : 2304;
    int j = blockIdx.x * 256 + threadIdx.x;
    if (j >= K) return;
    int chunk = H >> 3;
    int i0 = blockIdx.y * chunk;
    int i1 = i0 + chunk;
    float s = 0.f;
    for (int i = i0; i < i1; i++)
        s = fmaf(W[(size_t)i * K + j], __ldg(u + i), s);
    atomicAdd(t + j, s);
}

__global__ void sn_sk_all(const float* __restrict__ w1, const float* __restrict__ w2,
                          const float* __restrict__ ws) {
    const int wsel = blockIdx.y;
    const float* W = (wsel == 0) ? w1 : (wsel == 1) ? w2 : ws;
    const float* t = (wsel == 0) ? g_t1 : (wsel == 1) ? g_t2 : g_t3;
    const int H = (wsel == 0) ? 256 : 512;
    const int K = (wsel == 2) ? 256 : 2304;
    const int i = blockIdx.x;
    if (i >= H) return;
    float s = 0.f;
    for (int j = threadIdx.x; j < K; j += blockDim.x)
        s = fmaf(W[(size_t)i * K + j], __ldg(t + j), s);
    s = block_sum(s);
    if (threadIdx.x == 0) atomicAdd(&g_ns2[wsel], s * s);
    if (i == 0) {
        float a = 0.f;
        for (int j = threadIdx.x; j < K; j += blockDim.x) {
            float tv = __ldg(t + j);
            a = fmaf(tv, tv, a);
        }
        a = block_sum(a);
        if (threadIdx.x == 0) atomicAdd(&g_nt2[wsel], a);
    }
}

__global__ void sn_zero_tail() {
    int t = threadIdx.x;
    for (int i = t; i < 2304; i += 256) { g_t1[i] = 0.f; g_t2[i] = 0.f; }
    if (t < 256) g_t3[t] = 0.f;
    if (t < 3) { g_nt2[t] = 0.f; g_ns2[t] = 0.f; }
}

// ---------------- merged pad + weight prep ----------------
#define PAD_BLOCKS 8192
#define PREP_N1 (256 * 256 * 9)
#define PREP_N2 (512 * 256 * 9)
#define PREP_NS (512 * 256)
#define PREP_TOTAL (PREP_N1 + PREP_N2 + PREP_NS)
#define PREP_BLOCKS ((PREP_TOTAL + 255) / 256)
#define PADPREP_BLOCKS (PAD_BLOCKS + PREP_BLOCKS)

__global__ void padprep(const float* __restrict__ x, __half* __restrict__ xp,
                        const float* __restrict__ w1, const float* __restrict__ w2,
                        const float* __restrict__ ws) {
    __shared__ float sm[64][33];
    const int bid = blockIdx.x;
    const int tid = threadIdx.x;
    if (bid < PAD_BLOCKS) {
        const int wt = bid & 1;
        const int ict = (bid >> 1) & 3;
        const int plane = bid >> 3;
        const int img = plane >> 6, h = plane & 63;
        const int w0 = wt * 32, ic0 = ict * 64;
        const int icl = tid >> 5, wl = tid & 31;
        const float* xb = x + (((size_t)img * 256 + ic0) * 64 + h) * 64 + w0;
#pragma unroll
        for (int r = 0; r < 8; r++)
            sm[icl + r * 8][wl] = xb[(size_t)(icl + r * 8) * 4096 + wl];
        __syncthreads();
        const int wIdx = tid >> 3, icq = tid & 7;
        __half hv[8];
#pragma unroll
        for (int k = 0; k < 8; k++) hv[k] = __float2half_rn(sm[icq * 8 + k][wIdx]);
        *reinterpret_cast<int4*>(
            xp + (((size_t)img * 66 + h + 1) * 66 + (w0 + wIdx + 1)) * 256 + ic0 + icq * 8) =
            *reinterpret_cast<int4*>(hv);
    } else {
        int idx = (bid - PAD_BLOCKS) * 256 + tid;
        if (idx >= PREP_TOTAL) return;
        const float* w;
        __half* wtp;
        int KHW, li;
        if (idx < PREP_N1) {
            w = w1; wtp = g_wt1; KHW = 9; li = idx;
        } else if (idx < PREP_N1 + PREP_N2) {
            w = w2; wtp = g_wt2; KHW = 9; li = idx - PREP_N1;
        } else {
            w = ws; wtp = g_wts; KHW = 1; li = idx - PREP_N1 - PREP_N2;
        }
        int khw = li % KHW;
        int t = li / KHW;
        int ic = t & 255;
        int oc = t >> 8;
        wtp[((size_t)oc * KHW + khw) * 256 + ic] = __float2half_rn(w[li]);
    }
}

// ---------------- 4x4 binomial blur, NHWC, 4 x-outputs x 8ch per thread ------
template <bool CHECK, int OFF>
__global__ void blur4_nhwc(const __half* __restrict__ in, __half* __restrict__ out,
                           int inW, int outW, int groups) {
    int idx = blockIdx.x * blockDim.x + threadIdx.x;
    int total = 16 * outW * groups * 32;
    if (idx >= total) return;
    const int icq = idx & 31;
    int t = idx >> 5;
    const int xg = t % groups; t /= groups;
    const int y = t % outW;
    const int img = t / outW;
    const int x0 = xg * 4;
    const __half* ib = in + (size_t)img * inW * inW * 256 + icq * 8;
    const float kv[4] = {1.f, 3.f, 3.f, 1.f};
    float acc[4][8];
#pragma unroll
    for (int o = 0; o < 4; o++)
#pragma unroll
        for (int q = 0; q < 8; q++) acc[o][q] = 0.f;
#pragma unroll
    for (int i = 0; i < 4; i++) {
        const int yy = y + i + OFF;
        if ((unsigned)yy >= (unsigned)inW) continue;
        const __half* rb = ib + (size_t)yy * inW * 256;
#pragma unroll
        for (int c = 0; c < 7; c++) {
            const int xx = x0 + c + OFF;
            if ((unsigned)xx >= (unsigned)inW) continue;
            int4 v = *reinterpret_cast<const int4*>(rb + (size_t)xx * 256);
            const __half* h = reinterpret_cast<const __half*>(&v);
            float hv[8];
#pragma unroll
            for (int q = 0; q < 8; q++) hv[q] = __half2float(h[q]);
#pragma unroll
            for (int o = 0; o < 4; o++) {
                const int j = c - o;
                if (j >= 0 && j < 4) {
                    const float w = kv[i] * kv[j];
#pragma unroll
                    for (int q = 0; q < 8; q++) acc[o][q] = fmaf(w, hv[q], acc[o][q]);
                }
            }
        }
    }
#pragma unroll
    for (int o = 0; o < 4; o++) {
        const int x = x0 + o;
        if (x >= outW) break;
        __half res[8];
#pragma unroll
        for (int q = 0; q < 8; q++) res[q] = __float2half_rn(acc[o][q] * (1.f / 64.f));
        *reinterpret_cast<int4*>(
            out + ((size_t)img * outW * outW + (size_t)y * outW + x) * 256 + icq * 8) =
            *reinterpret_cast<int4*>(res);
    }
}

// ---------------------------------------------------------------------------
// fp16 mma.sync implicit-GEMM conv, NHWC, cp.async 3-stage ring, unrolled x3
// so each ring buffer base is a compile-time constant.
// EPI: 0 = *is + bias, lrelu -> NHWC fp16
//      1 = *is + bias, lrelu -> NCHW f32
//      2 = out*rsqrt2 + acc*is*rsqrt2 -> NCHW f32
// ---------------------------------------------------------------------------
#define STAGE_BYTES 20480
#define CONV_SMEM (3 * STAGE_BYTES)

template <int KHW, int STRIDE, int EPI, int NS>
__global__ void __launch_bounds__(256, 2) conv_hmma(
    const __half* __restrict__ in, const __half* __restrict__ wt,
    const float* __restrict__ bias, void* __restrict__ outv,
    int INROW, int INIMG, int OC, int OH, int OW, int sigIdx) {
    extern __shared__ char smem[];
    const uint32_t sb = smem_u32(smem);

    const int tid = threadIdx.x;
    const int lane = tid & 31;
    const int wid = tid >> 5;
    const int wm = wid & 3;
    const int wn = wid >> 2;

    const int m0 = blockIdx.x * 128;
    const int ocb = blockIdx.y * 128;
    const int ohw = OH * OW;
    const int img = m0 / ohw;
    const int rbase = m0 - img * ohw;

    const int mIdx = tid >> 1;
    const int kq = tid & 1;
    const int m = rbase + mIdx;
    const int oh = m / OW;
    const int ow = m - oh * OW;
    const __half* abase = in + (size_t)img * INIMG + (size_t)(oh * STRIDE) * INROW +
                          (size_t)(ow * STRIDE) * 256 + kq * 16;
    const __half* bbase = wt + (size_t)(ocb + mIdx) * KHW * 256 + kq * 16;
    const uint32_t stsOff = (uint32_t)(mIdx * 80 + kq * 32);

    const int lg = lane >> 3, lr = lane & 7;
    const uint32_t rowsel = (uint32_t)(lr + ((lg >> 1) << 3));
    const uint32_t kcol = (uint32_t)((lg & 1) << 4);
    const uint32_t aLMr = (wm * 32 + rowsel) * 80 + kcol;
    const uint32_t bLMr = (wn * 64 + rowsel) * 80 + kcol;

    float c[2][8][4];
#pragma unroll
    for (int mb = 0; mb < 2; mb++)
#pragma unroll
        for (int nb = 0; nb < 8; nb++)
#pragma unroll
            for (int q = 0; q < 4; q++) c[mb][nb][q] = 0.f;

    auto CPA = [&](int s, uint32_t base) {
        const int kk = s * 32;
        const int khw = (KHW == 1) ? 0 : (kk >> 8);
        const int ic0 = kk - (khw << 8);
        int kh = 0, kw = 0;
        if (KHW == 9) { kh = khw / 3; kw = khw - kh * 3; }
        const __half* ap = abase + (size_t)kh * INROW + kw * 256 + ic0;
        cpa16(base + stsOff, ap);
        cpa16(base + stsOff + 16, ap + 8);
        const __half* bp = bbase + khw * 256 + ic0;
        cpa16(base + 10240 + stsOff, bp);
        cpa16(base + 10240 + stsOff + 16, bp + 8);
        cp_commit();
    };

    auto MMA = [&](uint32_t base) {
        const uint32_t aLM = base + aLMr;
        const uint32_t bLM = base + 10240 + bLMr;
#pragma unroll
        for (int k16 = 0; k16 < 2; k16++) {
            uint32_t a[2][4], b[8][2];
#pragma unroll
            for (int mb = 0; mb < 2; mb++) {
                uint32_t r[4];
                ldsm4(r, aLM + k16 * 32 + mb * 1280);
                a[mb][0] = r[0]; a[mb][1] = r[2]; a[mb][2] = r[1]; a[mb][3] = r[3];
            }
#pragma unroll
            for (int nbp = 0; nbp < 4; nbp++) {
                uint32_t r[4];
                ldsm4(r, bLM + k16 * 32 + nbp * 1280);
                b[nbp * 2][0] = r[0]; b[nbp * 2][1] = r[1];
                b[nbp * 2 + 1][0] = r[2]; b[nbp * 2 + 1][1] = r[3];
            }
#pragma unroll
            for (int mb = 0; mb < 2; mb++)
#pragma unroll
                for (int nb = 0; nb < 8; nb++)
                    mma16816(c[mb][nb], a[mb], b[nb]);
        }
    };

    CPA(0, sb);
    if (NS > 1) CPA(1, sb + STAGE_BYTES);
    // stage loop unrolled by 3: ring buffer bases are compile-time constants
    for (int s0 = 0; s0 < NS; s0 += 3) {
#pragma unroll
        for (int j = 0; j < 3; j++) {
            const int s = s0 + j;
            if ((NS % 3 != 0) && s >= NS) break;
            if (s + 1 < NS) cp_wait<1>(); else cp_wait<0>();
            __syncthreads();
            if (s + 2 < NS) CPA(s + 2, sb + ((j + 2) % 3) * STAGE_BYTES);
            MMA(sb + j * STAGE_BYTES);
        }
    }
    __syncthreads();

    const float is = inv_sigma_of(sigIdx);
    const int erow = lane >> 2;
    const int ecolp = (lane & 3) * 2;

    if (EPI == 0) {
        __half* ob = (__half*)outv;
#pragma unroll
        for (int mb = 0; mb < 2; mb++) {
            const size_t mrow = (size_t)(m0 + wm * 32 + mb * 16 + erow);
#pragma unroll
            for (int nb = 0; nb < 8; nb++) {
                const int col = ocb + wn * 64 + nb * 8 + ecolp;
                const float bv0 = __ldg(bias + col);
                const float bv1 = __ldg(bias + col + 1);
                const float* cc = c[mb][nb];
                float v0 = fmaf(cc[0], is, bv0), v1 = fmaf(cc[1], is, bv1);
                float v2 = fmaf(cc[2], is, bv0), v3 = fmaf(cc[3], is, bv1);
                v0 = v0 > 0.f ? v0 : 0.2f * v0;
                v1 = v1 > 0.f ? v1 : 0.2f * v1;
                v2 = v2 > 0.f ? v2 : 0.2f * v2;
                v3 = v3 > 0.f ? v3 : 0.2f * v3;
                __half2 h0 = __floats2half2_rn(v0, v1);
                __half2 h1 = __floats2half2_rn(v2, v3);
                *reinterpret_cast<__half2*>(ob + mrow * 256 + col) = h0;
                *reinterpret_cast<__half2*>(ob + (mrow + 8) * 256 + col) = h1;
            }
        }
    } else {
        const float sc = is * RSQRT2;
        for (int nc = 0; nc < 4; nc++) {
            if (wn == (nc >> 1)) {
                const int nbBase = (nc & 1) * 4;
#pragma unroll
                for (int mb = 0; mb < 2; mb++) {
                    const int mrow = wm * 32 + mb * 16 + erow;
#pragma unroll
                    for (int j = 0; j < 4; j++) {
                        const int nb = nbBase + j;
                        const int ocl = j * 8 + ecolp;
                        const float* cc = c[mb][nb];
                        sts32f(sb + (uint32_t)(ocl * 544 + mrow * 4), cc[0]);
                        sts32f(sb + (uint32_t)((ocl + 1) * 544 + mrow * 4), cc[1]);
                        sts32f(sb + (uint32_t)(ocl * 544 + (mrow + 8) * 4), cc[2]);
                        sts32f(sb + (uint32_t)((ocl + 1) * 544 + (mrow + 8) * 4), cc[3]);
                    }
                }
            }
            __syncthreads();
#pragma unroll
            for (int p = 0; p < 4; p++) {
                const int idx = p * 256 + tid;
                const int ocl = idx >> 5;
                const int mq = (idx & 31) * 4;
                float4 v = lds128f(sb + (uint32_t)(ocl * 544 + mq * 4));
                const int oc = ocb + nc * 32 + ocl;
                const size_t go = ((size_t)img * OC + oc) * ohw + rbase + mq;
                if (EPI == 1) {
                    const float bv = __ldg(bias + oc);
                    v.x = fmaf(v.x, is, bv); v.y = fmaf(v.y, is, bv);
                    v.z = fmaf(v.z, is, bv); v.w = fmaf(v.w, is, bv);
                    v.x = v.x > 0.f ? v.x : 0.2f * v.x;
                    v.y = v.y > 0.f ? v.y : 0.2f * v.y;
                    v.z = v.z > 0.f ? v.z : 0.2f * v.z;
                    v.w = v.w > 0.f ? v.w : 0.2f * v.w;
                    *reinterpret_cast<float4*>((float*)outv + go) = v;
                } else {
                    float* op = (float*)outv + go;
                    float4 o = *reinterpret_cast<const float4*>(op);
                    o.x = fmaf(v.x, sc, o.x * RSQRT2);
                    o.y = fmaf(v.y, sc, o.y * RSQRT2);
                    o.z = fmaf(v.z, sc, o.z * RSQRT2);
                    o.w = fmaf(v.w, sc, o.w * RSQRT2);
                    *reinterpret_cast<float4*>(op) = o;
                }
            }
            __syncthreads();
        }
    }
}

// ---------------------------------------------------------------------------
extern "C" void kernel_launch(void* const* d_in, const int* in_sizes, int n_in,
                              void* d_out, int out_size) {
    const float* x   = (const float*)d_in[0];
    const float* w1  = (const float*)d_in[1];
    const float* u1  = (const float*)d_in[2];
    const float* b1  = (const float*)d_in[4];
    const float* w2  = (const float*)d_in[5];
    const float* u2  = (const float*)d_in[6];
    const float* b2  = (const float*)d_in[8];
    const float* wsk = (const float*)d_in[9];
    const float* us  = (const float*)d_in[10];
    float* out = (float*)d_out;

    __half *xpad, *bufA, *bufB, *bufC, *wt1, *wt2, *wts;
    cudaGetSymbolAddress((void**)&xpad, g_xpad);
    cudaGetSymbolAddress((void**)&bufA, g_bufA);
    cudaGetSymbolAddress((void**)&bufB, g_bufB);
    cudaGetSymbolAddress((void**)&bufC, g_bufC);
    cudaGetSymbolAddress((void**)&wt1, g_wt1);
    cudaGetSymbolAddress((void**)&wt2, g_wt2);
    cudaGetSymbolAddress((void**)&wts, g_wts);

    cudaFuncSetAttribute(conv_hmma<9, 1, 0, 72>,
                         cudaFuncAttributeMaxDynamicSharedMemorySize, CONV_SMEM);
    cudaFuncSetAttribute(conv_hmma<9, 2, 1, 72>,
                         cudaFuncAttributeMaxDynamicSharedMemorySize, CONV_SMEM);
    cudaFuncSetAttribute(conv_hmma<1, 2, 2, 8>,
                         cudaFuncAttributeMaxDynamicSharedMemorySize, CONV_SMEM);

    // #0: t = W^T u
    sn_tk_all<<<dim3(9, 8, 3), 256>>>(w1, u1, w2, u2, wsk, us);
    // #1: ||Wt||^2, ||t||^2
    sn_sk_all<<<dim3(512, 3), 256>>>(w1, w2, wsk);
    // #2: pad/transpose x + transpose/convert weights
    padprep<<<PADPREP_BLOCKS, 256>>>(x, xpad, w1, w2, wsk);
    // #3: conv1 (ncu sampling slot)
    conv_hmma<9, 1, 0, 72><<<dim3(512, 2), 256, CONV_SMEM>>>(
        xpad, wt1, b1, bufA, 66 * 256, 66 * 66 * 256, 256, 64, 64, 0);
    // #4: blurB (skip path): xpad (66) -> bufB (63), OFF=0
    {
        const int groups = (63 + 3) / 4;
        const int t = 16 * 63 * groups * 32;
        blur4_nhwc<false, 0><<<(t + 255) / 256, 256>>>(xpad, bufB, 66, 63, groups);
    }
    // #5: blurC: bufA (64) -> bufC (65), OFF=-2
    {
        const int groups = (65 + 3) / 4;
        const int t = 16 * 65 * groups * 32;
        blur4_nhwc<true, -2><<<(t + 255) / 256, 256>>>(bufA, bufC, 64, 65, groups);
    }
    // #6: conv2 -> out NCHW f32
    conv_hmma<9, 2, 1, 72><<<dim3(128, 4), 256, CONV_SMEM>>>(
        bufC, wt2, b2, out, 65 * 256, 65 * 65 * 256, 512, 32, 32, 1);
    // #7: skip conv: out = out*rsqrt2 + acc*is*rsqrt2
    conv_hmma<1, 2, 2, 8><<<dim3(128, 4), 256, CONV_SMEM>>>(
        bufB, wts, nullptr, out, 63 * 256, 63 * 63 * 256, 512, 32, 32, 2);
    // #8: reset SN accumulators for the next replay
    sn_zero_tail<<<1, 256>>>();
}